// round 14
// baseline (speedup 1.0000x reference)
#include <cuda_runtime.h>
#include <math.h>
#include <stdint.h>

#define NTOK 1569
#define BATCH 8
#define CDIM 768
#define NHEAD 12
#define HDIM 64
#define BH (BATCH*NHEAD)            /* 96 */
#define BHND (BH*NTOK*HDIM)         /* 9639936 */
#define NBC (NTOK*BATCH*CDIM)       /* 9639936 */

// ---------------- scratch (device globals: no allocation allowed) ----------
__device__ float g_q[BHND];
__device__ float g_k[BHND];
__device__ float g_v[BHND];
__device__ float g_xs[3*BHND];          // batched l2norm outputs
__device__ float g_t1[BHND];            // ori attention output
__device__ float g_t2[3*BHND];          // batched branch outputs
__device__ float g_rownorm[BATCH*NTOK];
__device__ float g_invtemp[BATCH];

// ---------------- helpers ---------------------------------------------------
__device__ __forceinline__ float to_tf32(float x) {
    uint32_t u;
    asm("cvt.rna.tf32.f32 %0, %1;" : "=r"(u) : "f"(x));
    return __uint_as_float(u);
}

__device__ __forceinline__ float ex2(float x) {
    float r;
    asm("ex2.approx.f32 %0, %1;" : "=f"(r) : "f"(x));
    return r;
}

__device__ __forceinline__ void mma8(float* c, uint32_t a0, uint32_t a1,
                                     uint32_t a2, uint32_t a3,
                                     uint32_t b0, uint32_t b1) {
    asm volatile(
        "mma.sync.aligned.m16n8k8.row.col.f32.tf32.tf32.f32 "
        "{%0,%1,%2,%3}, {%4,%5,%6,%7}, {%8,%9}, {%0,%1,%2,%3};"
        : "+f"(c[0]), "+f"(c[1]), "+f"(c[2]), "+f"(c[3])
        : "r"(a0), "r"(a1), "r"(a2), "r"(a3), "r"(b0), "r"(b1));
}

__device__ __forceinline__ uint32_t smem_u32(const void* p) {
    return (uint32_t)__cvta_generic_to_shared(p);
}
__device__ __forceinline__ void cp16(uint32_t dst, const void* src, bool pred) {
    int sz = pred ? 16 : 0;
    asm volatile("cp.async.ca.shared.global [%0], [%1], 16, %2;\n"
                 :: "r"(dst), "l"(src), "r"(sz));
}
__device__ __forceinline__ void cp_commit() {
    asm volatile("cp.async.commit_group;\n");
}
__device__ __forceinline__ void cp_wait1() {
    asm volatile("cp.async.wait_group 1;\n");
}
__device__ __forceinline__ void cp_wait0() {
    asm volatile("cp.async.wait_group 0;\n");
}

// ---------------- per-token L2 norm over C (for inv_temp) ------------------
__global__ void rownorm_kernel(const float* __restrict__ x) {
    int r = (blockIdx.x * blockDim.x + threadIdx.x) >> 5;
    int lane = threadIdx.x & 31;
    if (r >= BATCH * NTOK) return;
    int b = r / NTOK, n = r - b * NTOK;
    const float* p = x + (size_t)n * (BATCH * CDIM) + b * CDIM;
    float ss = 0.f;
#pragma unroll
    for (int kblk = 0; kblk < 6; kblk++) {
        float4 v = *(const float4*)(p + kblk * 128 + lane * 4);
        ss += v.x * v.x + v.y * v.y + v.z * v.z + v.w * v.w;
    }
#pragma unroll
    for (int o = 16; o; o >>= 1) ss += __shfl_xor_sync(0xffffffffu, ss, o);
    if (lane == 0) g_rownorm[r] = sqrtf(ss);
}

__global__ void invtemp_kernel() {
    __shared__ float sh[256];
    int b = blockIdx.x;
    float s = 0.f;
    for (int n = threadIdx.x; n < NTOK; n += 256) s += g_rownorm[b * NTOK + n];
    sh[threadIdx.x] = s;
    __syncthreads();
    for (int o = 128; o; o >>= 1) {
        if (threadIdx.x < o) sh[threadIdx.x] += sh[threadIdx.x + o];
        __syncthreads();
    }
    if (threadIdx.x == 0) g_invtemp[b] = (sh[0] / (float)NTOK) * 0.125f;
}

// ---------------- batched l2 normalize (3 sources), tf32-rounded output -----
__global__ void l2norm3_kernel(const float* __restrict__ p0,
                               const float* __restrict__ p1,
                               const float* __restrict__ p2,
                               float* __restrict__ out) {
    int r = (blockIdx.x * blockDim.x + threadIdx.x) >> 5;
    int lane = threadIdx.x & 31;
    if (r >= 3 * BH * NTOK) return;
    int z = r / (BH * NTOK);
    int rr = r - z * (BH * NTOK);
    const float* in = (z == 0) ? p0 : ((z == 1) ? p1 : p2);
    float2 v = *(const float2*)(in + (size_t)rr * HDIM + lane * 2);
    float ss = v.x * v.x + v.y * v.y;
#pragma unroll
    for (int o = 16; o; o >>= 1) ss += __shfl_xor_sync(0xffffffffu, ss, o);
    float inv = 1.f / fmaxf(sqrtf(ss), 1e-12f);
    *(float2*)(out + (size_t)r * HDIM + lane * 2) =
        make_float2(to_tf32(v.x * inv), to_tf32(v.y * inv));
}

// ---------------- flash attention (tf32 TC, cp.async double-buffer) ---------
// Block: 128 thr (4 warps). CTA Q-tile 128 rows; each warp 32 rows as two m16
// blocks sharing K/V fragments. K/V stream via cp.async into 2 buffers
// (K/V gmem operands are pre-rounded to tf32 by their producers).
// Strides: Q/P/K = 68 (bank 4g+t perm), V = 72 (bank 8t+g perm).
#define AST 68
#define VST 72
#define NT_TILES ((NTOK + 63) / 64)    /* 25 */
#define ATT_SMEM ((128*AST + 2*64*AST + 2*64*VST) * 4)

__global__ __launch_bounds__(128) void attn_tc(
    const float* __restrict__ Q, const float* __restrict__ K,
    const float* __restrict__ V, float* __restrict__ O,
    int useInvTemp, float cscale, int zsQ, int zsV) {
    extern __shared__ float sm[];
    float* Ps = sm;                         // 128 x AST: Q staging, then P
    float* Kb[2] = { sm + 128 * AST, sm + 128 * AST + 64 * AST };
    float* Vb[2] = { sm + 128 * AST + 2 * 64 * AST,
                     sm + 128 * AST + 2 * 64 * AST + 64 * VST };

    size_t zq = (size_t)blockIdx.z * zsQ;
    Q += zq; K += zq; O += zq;
    V += (size_t)blockIdx.z * zsV;

    int tid = threadIdx.x;
    int warp = tid >> 5, lane = tid & 31;
    int g = lane >> 2, t = lane & 3;
    int bh = blockIdx.y;
    int m0 = blockIdx.x * 128;
    float scale = useInvTemp ? g_invtemp[bh / NHEAD] : cscale;
    const float qscale = scale * 1.4426950408889634f;  // fold log2(e) for ex2
    const size_t base = (size_t)bh * NTOK * HDIM;
    const int rA = warp * 32 + g;
    const int rB = warp * 32 + 16 + g;

    // ---- kick off K/V tile 0 loads ----
    {
#pragma unroll
        for (int e = 0; e < 8; e++) {
            int idx = tid + e * 128;
            int row = idx >> 4;
            int d = (idx & 15) << 2;
            bool p = row < NTOK;   // kt0 = 0
            cp16(smem_u32(&Kb[0][row * AST + d]), K + base + (size_t)row * HDIM + d, p);
            cp16(smem_u32(&Vb[0][row * VST + d]), V + base + (size_t)row * HDIM + d, p);
        }
        cp_commit();
    }

    // ---- stage Q (scaled, rounded) into Ps ----
#pragma unroll
    for (int e = 0; e < 16; e++) {
        int idx = tid + e * 128;
        int row = idx >> 4;
        int d = (idx & 15) << 2;
        float4 qv = make_float4(0.f, 0.f, 0.f, 0.f);
        if (m0 + row < NTOK)
            qv = *(const float4*)(Q + base + (size_t)(m0 + row) * HDIM + d);
        float4 w;
        w.x = to_tf32(qv.x * qscale); w.y = to_tf32(qv.y * qscale);
        w.z = to_tf32(qv.z * qscale); w.w = to_tf32(qv.w * qscale);
        *(float4*)&Ps[row * AST + d] = w;
    }
    __syncthreads();

    // ---- hoist Q fragments for both m-blocks into registers ----
    uint32_t qA[8][4], qB[8][4];
    {
        const uint32_t* pu = (const uint32_t*)Ps;
#pragma unroll
        for (int kt = 0; kt < 8; kt++) {
            qA[kt][0] = pu[rA * AST + kt * 8 + t];
            qA[kt][1] = pu[(rA + 8) * AST + kt * 8 + t];
            qA[kt][2] = pu[rA * AST + kt * 8 + t + 4];
            qA[kt][3] = pu[(rA + 8) * AST + kt * 8 + t + 4];
            qB[kt][0] = pu[rB * AST + kt * 8 + t];
            qB[kt][1] = pu[(rB + 8) * AST + kt * 8 + t];
            qB[kt][2] = pu[rB * AST + kt * 8 + t + 4];
            qB[kt][3] = pu[(rB + 8) * AST + kt * 8 + t + 4];
        }
    }
    __syncthreads();   // Ps reads done before softmax overwrites

    float lA0 = 0.f, lA1 = 0.f, lB0 = 0.f, lB1 = 0.f;
    float oA[8][4], oB[8][4];
#pragma unroll
    for (int nt = 0; nt < 8; nt++)
#pragma unroll
        for (int j = 0; j < 4; j++) { oA[nt][j] = 0.f; oB[nt][j] = 0.f; }

    for (int i = 0; i < NT_TILES; i++) {
        int cur = i & 1;
        int kt0 = i * 64;
        // issue next tile into the other buffer (its readers finished at the
        // __syncthreads ending iteration i-1)
        if (i + 1 < NT_TILES) {
            int nkt0 = kt0 + 64;
#pragma unroll
            for (int e = 0; e < 8; e++) {
                int idx = tid + e * 128;
                int row = idx >> 4;
                int d = (idx & 15) << 2;
                bool p = (nkt0 + row) < NTOK;
                int rr = p ? (nkt0 + row) : (NTOK - 1);
                cp16(smem_u32(&Kb[1 - cur][row * AST + d]),
                     K + base + (size_t)rr * HDIM + d, p);
                cp16(smem_u32(&Vb[1 - cur][row * VST + d]),
                     V + base + (size_t)rr * HDIM + d, p);
            }
            cp_commit();
            cp_wait1();
        } else {
            cp_wait0();
        }
        __syncthreads();   // tile i data visible to all warps

        const uint32_t* ku = (const uint32_t*)Kb[cur];
        const uint32_t* vu = (const uint32_t*)Vb[cur];

        // ---- S = (Q*qscale) K^T  (both m-blocks share B fragments) ----
        float sA[8][4], sB[8][4];
#pragma unroll
        for (int nt = 0; nt < 8; nt++)
#pragma unroll
            for (int j = 0; j < 4; j++) { sA[nt][j] = 0.f; sB[nt][j] = 0.f; }

#pragma unroll
        for (int kt = 0; kt < 8; kt++) {
#pragma unroll
            for (int nt = 0; nt < 8; nt++) {
                uint32_t b0 = ku[(nt * 8 + g) * AST + kt * 8 + t];
                uint32_t b1 = ku[(nt * 8 + g) * AST + kt * 8 + t + 4];
                mma8(sA[nt], qA[kt][0], qA[kt][1], qA[kt][2], qA[kt][3], b0, b1);
                mma8(sB[nt], qB[kt][0], qB[kt][1], qB[kt][2], qB[kt][3], b0, b1);
            }
        }

        // ---- no-max softmax: p = 2^s ----
        bool tail = (kt0 + 64 > NTOK);
#pragma unroll
        for (int nt = 0; nt < 8; nt++) {
            if (tail) {
                int cg = kt0 + nt * 8 + 2 * t;
                if (cg >= NTOK) {
                    sA[nt][0] = -1e30f; sA[nt][2] = -1e30f;
                    sB[nt][0] = -1e30f; sB[nt][2] = -1e30f;
                }
                if (cg + 1 >= NTOK) {
                    sA[nt][1] = -1e30f; sA[nt][3] = -1e30f;
                    sB[nt][1] = -1e30f; sB[nt][3] = -1e30f;
                }
            }
            float pA0 = ex2(sA[nt][0]);
            float pA1 = ex2(sA[nt][1]);
            float pA2 = ex2(sA[nt][2]);
            float pA3 = ex2(sA[nt][3]);
            float pB0 = ex2(sB[nt][0]);
            float pB1 = ex2(sB[nt][1]);
            float pB2 = ex2(sB[nt][2]);
            float pB3 = ex2(sB[nt][3]);
            lA0 += pA0 + pA1; lA1 += pA2 + pA3;
            lB0 += pB0 + pB1; lB1 += pB2 + pB3;
            int col = nt * 8 + 2 * t;
            *(float2*)&Ps[rA * AST + col]       = make_float2(to_tf32(pA0), to_tf32(pA1));
            *(float2*)&Ps[(rA + 8) * AST + col] = make_float2(to_tf32(pA2), to_tf32(pA3));
            *(float2*)&Ps[rB * AST + col]       = make_float2(to_tf32(pB0), to_tf32(pB1));
            *(float2*)&Ps[(rB + 8) * AST + col] = make_float2(to_tf32(pB2), to_tf32(pB3));
        }
        __syncwarp();

        // ---- O += P V  (both m-blocks share B fragments) ----
        const uint32_t* pu = (const uint32_t*)Ps;
#pragma unroll
        for (int kt = 0; kt < 8; kt++) {
            uint32_t aA0 = pu[rA * AST + kt * 8 + t];
            uint32_t aA1 = pu[(rA + 8) * AST + kt * 8 + t];
            uint32_t aA2 = pu[rA * AST + kt * 8 + t + 4];
            uint32_t aA3 = pu[(rA + 8) * AST + kt * 8 + t + 4];
            uint32_t aB0 = pu[rB * AST + kt * 8 + t];
            uint32_t aB1 = pu[(rB + 8) * AST + kt * 8 + t];
            uint32_t aB2 = pu[rB * AST + kt * 8 + t + 4];
            uint32_t aB3 = pu[(rB + 8) * AST + kt * 8 + t + 4];
#pragma unroll
            for (int nt = 0; nt < 8; nt++) {
                uint32_t b0 = vu[(kt * 8 + t) * VST + nt * 8 + g];
                uint32_t b1 = vu[(kt * 8 + t + 4) * VST + nt * 8 + g];
                mma8(oA[nt], aA0, aA1, aA2, aA3, b0, b1);
                mma8(oB[nt], aB0, aB1, aB2, aB3, b0, b1);
            }
        }
        __syncthreads();   // all warps done with buf[cur] before it is refilled
    }

    // deferred l reduction over the 4 t-lanes of each row group
    lA0 += __shfl_xor_sync(0xffffffffu, lA0, 1);
    lA0 += __shfl_xor_sync(0xffffffffu, lA0, 2);
    lA1 += __shfl_xor_sync(0xffffffffu, lA1, 1);
    lA1 += __shfl_xor_sync(0xffffffffu, lA1, 2);
    lB0 += __shfl_xor_sync(0xffffffffu, lB0, 1);
    lB0 += __shfl_xor_sync(0xffffffffu, lB0, 2);
    lB1 += __shfl_xor_sync(0xffffffffu, lB1, 1);
    lB1 += __shfl_xor_sync(0xffffffffu, lB1, 2);
    float iA0 = 1.f / lA0, iA1 = 1.f / lA1, iB0 = 1.f / lB0, iB1 = 1.f / lB1;
#pragma unroll
    for (int nt = 0; nt < 8; nt++) {
        int col = nt * 8 + 2 * t;
        int r;
        r = m0 + rA;
        if (r < NTOK)
            *(float2*)(O + base + (size_t)r * HDIM + col) =
                make_float2(oA[nt][0] * iA0, oA[nt][1] * iA0);
        r = m0 + rA + 8;
        if (r < NTOK)
            *(float2*)(O + base + (size_t)r * HDIM + col) =
                make_float2(oA[nt][2] * iA1, oA[nt][3] * iA1);
        r = m0 + rB;
        if (r < NTOK)
            *(float2*)(O + base + (size_t)r * HDIM + col) =
                make_float2(oB[nt][0] * iB0, oB[nt][1] * iB0);
        r = m0 + rB + 8;
        if (r < NTOK)
            *(float2*)(O + base + (size_t)r * HDIM + col) =
                make_float2(oB[nt][2] * iB1, oB[nt][3] * iB1);
    }
}

// ---------------- qkv projection GEMM (tf32 TC), tf32-rounded outputs -------
#define GST 36

__global__ __launch_bounds__(128) void qkv_tc(const float* __restrict__ x,
                                              const float* __restrict__ W) {
    __shared__ float As[64 * GST];
    __shared__ float Bs[64 * GST];
    int tid = threadIdx.x;
    int warp = tid >> 5, lane = tid & 31;
    int g = lane >> 2, t = lane & 3;
    int m0 = blockIdx.x * 64;
    int o0 = blockIdx.y * 64;
    int b = blockIdx.z;
    const int r0 = warp * 16 + g;

    float c[8][4];
#pragma unroll
    for (int nt = 0; nt < 8; nt++)
#pragma unroll
        for (int j = 0; j < 4; j++) c[nt][j] = 0.f;

    for (int c0 = 0; c0 < CDIM; c0 += 32) {
        __syncthreads();
#pragma unroll
        for (int e = 0; e < 4; e++) {
            int idx = tid + e * 128;
            int row = idx >> 3;
            int cs = (idx & 7) << 2;
            float4 a4 = make_float4(0.f, 0.f, 0.f, 0.f);
            if (m0 + row < NTOK)
                a4 = *(const float4*)(x + (size_t)(m0 + row) * (BATCH * CDIM) + b * CDIM + c0 + cs);
            float4 aw;
            aw.x = to_tf32(a4.x); aw.y = to_tf32(a4.y);
            aw.z = to_tf32(a4.z); aw.w = to_tf32(a4.w);
            *(float4*)&As[row * GST + cs] = aw;
            float4 b4 = *(const float4*)(W + (size_t)(o0 + row) * CDIM + c0 + cs);
            float4 bw;
            bw.x = to_tf32(b4.x); bw.y = to_tf32(b4.y);
            bw.z = to_tf32(b4.z); bw.w = to_tf32(b4.w);
            *(float4*)&Bs[row * GST + cs] = bw;
        }
        __syncthreads();

        const uint32_t* au = (const uint32_t*)As;
        const uint32_t* bu = (const uint32_t*)Bs;
#pragma unroll
        for (int kt = 0; kt < 4; kt++) {
            uint32_t a0 = au[r0 * GST + kt * 8 + t];
            uint32_t a1 = au[(r0 + 8) * GST + kt * 8 + t];
            uint32_t a2 = au[r0 * GST + kt * 8 + t + 4];
            uint32_t a3 = au[(r0 + 8) * GST + kt * 8 + t + 4];
#pragma unroll
            for (int nt = 0; nt < 8; nt++) {
                uint32_t b0 = bu[(nt * 8 + g) * GST + kt * 8 + t];
                uint32_t b1 = bu[(nt * 8 + g) * GST + kt * 8 + t + 4];
                mma8(c[nt], a0, a1, a2, a3, b0, b1);
            }
        }
    }

    int tsel = o0 / CDIM;
    int h = (o0 % CDIM) >> 6;
    float* dst = (tsel == 0) ? g_q : ((tsel == 1) ? g_k : g_v);
    dst += (size_t)((b * NHEAD + h) * NTOK) * HDIM;
    int gr0 = m0 + r0, gr1 = m0 + r0 + 8;
#pragma unroll
    for (int nt = 0; nt < 8; nt++) {
        int col = nt * 8 + 2 * t;
        if (gr0 < NTOK)
            *(float2*)&dst[(size_t)gr0 * HDIM + col] =
                make_float2(to_tf32(c[nt][0]), to_tf32(c[nt][1]));
        if (gr1 < NTOK)
            *(float2*)&dst[(size_t)gr1 * HDIM + col] =
                make_float2(to_tf32(c[nt][2]), to_tf32(c[nt][3]));
    }
}

// ---------------- output projection GEMM (tf32 TC; optional 3-way sum) ------
// If s1/s2 non-null: A-tile = s0+s1+s2 (fp32 adds, then one tf32 round).
__global__ __launch_bounds__(128) void proj_tc(const float* __restrict__ s0,
                                               const float* __restrict__ s1,
                                               const float* __restrict__ s2,
                                               const float* __restrict__ W,
                                               const float* __restrict__ bias,
                                               float* __restrict__ out,
                                               float prescale) {
    __shared__ float As[64 * GST];
    __shared__ float Bs[64 * GST];
    int tid = threadIdx.x;
    int warp = tid >> 5, lane = tid & 31;
    int g = lane >> 2, t = lane & 3;
    int m0 = blockIdx.x * 64;
    int o0 = blockIdx.y * 64;
    int b = blockIdx.z;
    const int r0 = warp * 16 + g;

    float c[8][4];
#pragma unroll
    for (int nt = 0; nt < 8; nt++)
#pragma unroll
        for (int j = 0; j < 4; j++) c[nt][j] = 0.f;

    for (int c0 = 0; c0 < CDIM; c0 += 32) {
        int h = c0 >> 6;
        int dlo = c0 & 63;
        __syncthreads();
#pragma unroll
        for (int e = 0; e < 4; e++) {
            int idx = tid + e * 128;
            int row = idx >> 3;
            int cs = (idx & 7) << 2;
            float4 a4 = make_float4(0.f, 0.f, 0.f, 0.f);
            if (m0 + row < NTOK) {
                size_t off = (size_t)((b * NHEAD + h) * NTOK + m0 + row) * HDIM + dlo + cs;
                a4 = *(const float4*)(s0 + off);
                if (s1) {
                    float4 a1 = *(const float4*)(s1 + off);
                    float4 a2 = *(const float4*)(s2 + off);
                    a4.x += a1.x + a2.x; a4.y += a1.y + a2.y;
                    a4.z += a1.z + a2.z; a4.w += a1.w + a2.w;
                }
            }
            float4 aw;
            aw.x = to_tf32(a4.x); aw.y = to_tf32(a4.y);
            aw.z = to_tf32(a4.z); aw.w = to_tf32(a4.w);
            *(float4*)&As[row * GST + cs] = aw;
            float4 b4 = *(const float4*)(W + (size_t)(o0 + row) * CDIM + c0 + cs);
            float4 bw;
            bw.x = to_tf32(b4.x); bw.y = to_tf32(b4.y);
            bw.z = to_tf32(b4.z); bw.w = to_tf32(b4.w);
            *(float4*)&Bs[row * GST + cs] = bw;
        }
        __syncthreads();

        const uint32_t* au = (const uint32_t*)As;
        const uint32_t* bu = (const uint32_t*)Bs;
#pragma unroll
        for (int kt = 0; kt < 4; kt++) {
            uint32_t a0 = au[r0 * GST + kt * 8 + t];
            uint32_t a1 = au[(r0 + 8) * GST + kt * 8 + t];
            uint32_t a2 = au[r0 * GST + kt * 8 + t + 4];
            uint32_t a3 = au[(r0 + 8) * GST + kt * 8 + t + 4];
#pragma unroll
            for (int nt = 0; nt < 8; nt++) {
                uint32_t b0 = bu[(nt * 8 + g) * GST + kt * 8 + t];
                uint32_t b1 = bu[(nt * 8 + g) * GST + kt * 8 + t + 4];
                mma8(c[nt], a0, a1, a2, a3, b0, b1);
            }
        }
    }

    int gr0 = m0 + r0, gr1 = m0 + r0 + 8;
#pragma unroll
    for (int nt = 0; nt < 8; nt++) {
        int col = nt * 8 + 2 * t;
        float b0 = bias[o0 + col], b1 = bias[o0 + col + 1];
        if (gr0 < NTOK)
            *(float2*)(out + (size_t)gr0 * (BATCH * CDIM) + b * CDIM + o0 + col) =
                make_float2(c[nt][0] * prescale + b0, c[nt][1] * prescale + b1);
        if (gr1 < NTOK)
            *(float2*)(out + (size_t)gr1 * (BATCH * CDIM) + b * CDIM + o0 + col) =
                make_float2(c[nt][2] * prescale + b0, c[nt][3] * prescale + b1);
    }
}

// ---------------- host orchestration ---------------------------------------
extern "C" void kernel_launch(void* const* d_in, const int* in_sizes, int n_in,
                              void* d_out, int out_size) {
    const float* x = (const float*)d_in[0];
    const float* Wqkv = (const float*)d_in[1];
    const float* Wproj = (const float*)d_in[2];
    const float* bproj = (const float*)d_in[3];
    float* out = (float*)d_out;

    cudaFuncSetAttribute(attn_tc, cudaFuncAttributeMaxDynamicSharedMemorySize,
                         ATT_SMEM);

    float *q, *k, *v, *xs, *t1, *t2;
    cudaGetSymbolAddress((void**)&q, g_q);
    cudaGetSymbolAddress((void**)&k, g_k);
    cudaGetSymbolAddress((void**)&v, g_v);
    cudaGetSymbolAddress((void**)&xs, g_xs);
    cudaGetSymbolAddress((void**)&t1, g_t1);
    cudaGetSymbolAddress((void**)&t2, g_t2);

    const int LN3_GRID = (3 * BH * NTOK * 32 + 255) / 256;
    dim3 ga((NTOK + 127) / 128, BH, 1);    // 13 x 96 (ori)
    dim3 gab((NTOK + 127) / 128, BH, 3);   // 13 x 96 x 3 (batched branches)
    dim3 gq((NTOK + 63) / 64, 36, BATCH);
    dim3 gp((NTOK + 63) / 64, 12, BATCH);

    rownorm_kernel<<<(BATCH * NTOK * 32 + 255) / 256, 256>>>(x);
    invtemp_kernel<<<BATCH, 256>>>();

    qkv_tc<<<gq, 128>>>(x, Wqkv);

    // original attention -> x_ori (second half of output)
    attn_tc<<<ga, 128, ATT_SMEM>>>(q, k, v, t1, 0, 0.125f, 0, 0);
    proj_tc<<<gp, 128>>>(t1, nullptr, nullptr, Wproj, bproj, out + NBC, 1.0f);

    // batched branches: z=0 -> v, z=1 -> k, z=2 -> q
    l2norm3_kernel<<<LN3_GRID, 256>>>(v, k, q, xs);
    attn_tc<<<gab, 128, ATT_SMEM>>>(xs, xs, xs, t2, 1, 0.f, BHND, BHND);
    l2norm3_kernel<<<LN3_GRID, 256>>>(t2, t2 + BHND, t2 + 2 * BHND, xs);
    attn_tc<<<gab, 128, ATT_SMEM>>>(xs, xs, v, t2, 1, 0.f, BHND, 0);

    // x_out = ((b_v + b_k + b_q)/3) @ Wproj^T + bproj  (first half of output)
    proj_tc<<<gp, 128>>>(t2, t2 + BHND, t2 + 2 * BHND, Wproj, bproj, out,
                         1.0f / 3.0f);
}

// round 15
// speedup vs baseline: 1.6282x; 1.6282x over previous
#include <cuda_runtime.h>
#include <math.h>
#include <stdint.h>

#define NTOK 1569
#define BATCH 8
#define CDIM 768
#define NHEAD 12
#define HDIM 64
#define BH (BATCH*NHEAD)            /* 96 */
#define BHND (BH*NTOK*HDIM)         /* 9639936 */
#define NBC (NTOK*BATCH*CDIM)       /* 9639936 */

// ---------------- scratch (device globals: no allocation allowed) ----------
__device__ float g_q[BHND];
__device__ float g_k[BHND];
__device__ float g_v[BHND];
__device__ float g_xs[3*BHND];          // batched l2norm outputs
__device__ float g_t1[BHND];            // ori attention output
__device__ float g_t2[3*BHND];          // batched branch outputs
__device__ float g_rownorm[BATCH*NTOK];
__device__ float g_invtemp[BATCH];

// ---------------- tf32 helpers ---------------------------------------------
__device__ __forceinline__ float to_tf32(float x) {
    uint32_t u;
    asm("cvt.rna.tf32.f32 %0, %1;" : "=r"(u) : "f"(x));
    return __uint_as_float(u);
}

__device__ __forceinline__ float ex2(float x) {
    float r;
    asm("ex2.approx.f32 %0, %1;" : "=f"(r) : "f"(x));
    return r;
}

__device__ __forceinline__ void mma8(float* c, uint32_t a0, uint32_t a1,
                                     uint32_t a2, uint32_t a3,
                                     uint32_t b0, uint32_t b1) {
    asm volatile(
        "mma.sync.aligned.m16n8k8.row.col.f32.tf32.tf32.f32 "
        "{%0,%1,%2,%3}, {%4,%5,%6,%7}, {%8,%9}, {%0,%1,%2,%3};"
        : "+f"(c[0]), "+f"(c[1]), "+f"(c[2]), "+f"(c[3])
        : "r"(a0), "r"(a1), "r"(a2), "r"(a3), "r"(b0), "r"(b1));
}

// ---------------- per-token L2 norm over C (for inv_temp) ------------------
__global__ void rownorm_kernel(const float* __restrict__ x) {
    int r = (blockIdx.x * blockDim.x + threadIdx.x) >> 5;
    int lane = threadIdx.x & 31;
    if (r >= BATCH * NTOK) return;
    int b = r / NTOK, n = r - b * NTOK;
    const float* p = x + (size_t)n * (BATCH * CDIM) + b * CDIM;
    float ss = 0.f;
#pragma unroll
    for (int kblk = 0; kblk < 6; kblk++) {
        float4 v = *(const float4*)(p + kblk * 128 + lane * 4);
        ss += v.x * v.x + v.y * v.y + v.z * v.z + v.w * v.w;
    }
#pragma unroll
    for (int o = 16; o; o >>= 1) ss += __shfl_xor_sync(0xffffffffu, ss, o);
    if (lane == 0) g_rownorm[r] = sqrtf(ss);
}

__global__ void invtemp_kernel() {
    __shared__ float sh[256];
    int b = blockIdx.x;
    float s = 0.f;
    for (int n = threadIdx.x; n < NTOK; n += 256) s += g_rownorm[b * NTOK + n];
    sh[threadIdx.x] = s;
    __syncthreads();
    for (int o = 128; o; o >>= 1) {
        if (threadIdx.x < o) sh[threadIdx.x] += sh[threadIdx.x + o];
        __syncthreads();
    }
    if (threadIdx.x == 0) g_invtemp[b] = (sh[0] / (float)NTOK) * 0.125f;
}

// ---------------- batched l2 normalize (3 sources -> contiguous out) --------
__global__ void l2norm3_kernel(const float* __restrict__ p0,
                               const float* __restrict__ p1,
                               const float* __restrict__ p2,
                               float* __restrict__ out) {
    int r = (blockIdx.x * blockDim.x + threadIdx.x) >> 5;
    int lane = threadIdx.x & 31;
    if (r >= 3 * BH * NTOK) return;
    int z = r / (BH * NTOK);
    int rr = r - z * (BH * NTOK);
    const float* in = (z == 0) ? p0 : ((z == 1) ? p1 : p2);
    float2 v = *(const float2*)(in + (size_t)rr * HDIM + lane * 2);
    float ss = v.x * v.x + v.y * v.y;
#pragma unroll
    for (int o = 16; o; o >>= 1) ss += __shfl_xor_sync(0xffffffffu, ss, o);
    float inv = 1.f / fmaxf(sqrtf(ss), 1e-12f);
    *(float2*)(out + (size_t)r * HDIM + lane * 2) = make_float2(v.x * inv, v.y * inv);
}

// ---------------- flash attention (tf32 tensor-core, M=32/warp) -------------
// Interior identical to the 3830us R12 kernel. Prologue selects per-z operand
// pointers so ONE launch covers ori + all three ss-branches (stage 0), or the
// three second-stage branch attentions (stage 1).
#define AST 68
#define VST 72
#define ATT_SMEM ((128*AST + 64*AST + 64*VST) * 4)

__global__ __launch_bounds__(128) void attn_tc(
    const float* __restrict__ q0, const float* __restrict__ k0,
    const float* __restrict__ v0, const float* __restrict__ xs,
    float* __restrict__ t1, float* __restrict__ t2, int stage) {
    extern __shared__ float sm[];
    float* Ps = sm;                       // 128 x AST: Q staging, then P
    float* Ks = sm + 128 * AST;           // 64 x AST
    float* Vs = sm + 128 * AST + 64 * AST;// 64 x VST

    // ---- per-z operand selection ----
    const float *Q, *K, *V;
    float* O;
    int useInvTemp;
    int z = blockIdx.z;
    if (stage == 0) {
        if (z == 0) {                      // original attention
            Q = q0; K = k0; V = v0; O = t1; useInvTemp = 0;
        } else {                           // branch stage-1: xs self-attn
            const float* p = xs + (size_t)(z - 1) * BHND;
            Q = p; K = p; V = p;
            O = t2 + (size_t)(z - 1) * BHND;
            useInvTemp = 1;
        }
    } else {                               // branch stage-2: xs self vs v
        const float* p = xs + (size_t)z * BHND;
        Q = p; K = p; V = v0;
        O = t2 + (size_t)z * BHND;
        useInvTemp = 1;
    }

    int tid = threadIdx.x;
    int warp = tid >> 5, lane = tid & 31;
    int g = lane >> 2, t = lane & 3;
    int bh = blockIdx.y;
    int m0 = blockIdx.x * 128;
    float scale = useInvTemp ? g_invtemp[bh / NHEAD] : 0.125f;
    const float qscale = scale * 1.4426950408889634f;  // fold log2(e) for ex2
    const size_t base = (size_t)bh * NTOK * HDIM;
    const int rA = warp * 32 + g;
    const int rB = warp * 32 + 16 + g;

    // ---- stage Q (scaled, tf32) into Ps ----
#pragma unroll
    for (int e = 0; e < 16; e++) {
        int idx = tid + e * 128;
        int row = idx >> 4;
        int d = (idx & 15) << 2;
        float4 qv = make_float4(0.f, 0.f, 0.f, 0.f);
        if (m0 + row < NTOK)
            qv = *(const float4*)(Q + base + (size_t)(m0 + row) * HDIM + d);
        float4 w;
        w.x = to_tf32(qv.x * qscale); w.y = to_tf32(qv.y * qscale);
        w.z = to_tf32(qv.z * qscale); w.w = to_tf32(qv.w * qscale);
        *(float4*)&Ps[row * AST + d] = w;
    }
    __syncthreads();

    // ---- hoist Q fragments for both m-blocks into registers ----
    uint32_t qA[8][4], qB[8][4];
    {
        const uint32_t* pu = (const uint32_t*)Ps;
#pragma unroll
        for (int kt = 0; kt < 8; kt++) {
            qA[kt][0] = pu[rA * AST + kt * 8 + t];
            qA[kt][1] = pu[(rA + 8) * AST + kt * 8 + t];
            qA[kt][2] = pu[rA * AST + kt * 8 + t + 4];
            qA[kt][3] = pu[(rA + 8) * AST + kt * 8 + t + 4];
            qB[kt][0] = pu[rB * AST + kt * 8 + t];
            qB[kt][1] = pu[(rB + 8) * AST + kt * 8 + t];
            qB[kt][2] = pu[rB * AST + kt * 8 + t + 4];
            qB[kt][3] = pu[(rB + 8) * AST + kt * 8 + t + 4];
        }
    }

    float lA0 = 0.f, lA1 = 0.f, lB0 = 0.f, lB1 = 0.f;
    float oA[8][4], oB[8][4];
#pragma unroll
    for (int nt = 0; nt < 8; nt++)
#pragma unroll
        for (int j = 0; j < 4; j++) { oA[nt][j] = 0.f; oB[nt][j] = 0.f; }

    for (int kt0 = 0; kt0 < NTOK; kt0 += 64) {
        __syncthreads();
#pragma unroll
        for (int e = 0; e < 8; e++) {
            int idx = tid + e * 128;
            int row = idx >> 4;
            int d = (idx & 15) << 2;
            float4 kv = make_float4(0.f, 0.f, 0.f, 0.f);
            float4 vv = make_float4(0.f, 0.f, 0.f, 0.f);
            if (kt0 + row < NTOK) {
                kv = *(const float4*)(K + base + (size_t)(kt0 + row) * HDIM + d);
                vv = *(const float4*)(V + base + (size_t)(kt0 + row) * HDIM + d);
            }
            float4 kw, vw;
            kw.x = to_tf32(kv.x); kw.y = to_tf32(kv.y);
            kw.z = to_tf32(kv.z); kw.w = to_tf32(kv.w);
            vw.x = to_tf32(vv.x); vw.y = to_tf32(vv.y);
            vw.z = to_tf32(vv.z); vw.w = to_tf32(vv.w);
            *(float4*)&Ks[row * AST + d] = kw;
            *(float4*)&Vs[row * VST + d] = vw;
        }
        __syncthreads();

        // ---- S = (Q*qscale) K^T  (both m-blocks share B fragments) ----
        float sA[8][4], sB[8][4];
#pragma unroll
        for (int nt = 0; nt < 8; nt++)
#pragma unroll
            for (int j = 0; j < 4; j++) { sA[nt][j] = 0.f; sB[nt][j] = 0.f; }

        const uint32_t* ku = (const uint32_t*)Ks;
#pragma unroll
        for (int kt = 0; kt < 8; kt++) {
#pragma unroll
            for (int nt = 0; nt < 8; nt++) {
                uint32_t b0 = ku[(nt * 8 + g) * AST + kt * 8 + t];
                uint32_t b1 = ku[(nt * 8 + g) * AST + kt * 8 + t + 4];
                mma8(sA[nt], qA[kt][0], qA[kt][1], qA[kt][2], qA[kt][3], b0, b1);
                mma8(sB[nt], qB[kt][0], qB[kt][1], qB[kt][2], qB[kt][3], b0, b1);
            }
        }

        // ---- no-max softmax: p = 2^s ----
        bool tail = (kt0 + 64 > NTOK);
#pragma unroll
        for (int nt = 0; nt < 8; nt++) {
            if (tail) {
                int cg = kt0 + nt * 8 + 2 * t;
                if (cg >= NTOK) {
                    sA[nt][0] = -1e30f; sA[nt][2] = -1e30f;
                    sB[nt][0] = -1e30f; sB[nt][2] = -1e30f;
                }
                if (cg + 1 >= NTOK) {
                    sA[nt][1] = -1e30f; sA[nt][3] = -1e30f;
                    sB[nt][1] = -1e30f; sB[nt][3] = -1e30f;
                }
            }
            float pA0 = ex2(sA[nt][0]);
            float pA1 = ex2(sA[nt][1]);
            float pA2 = ex2(sA[nt][2]);
            float pA3 = ex2(sA[nt][3]);
            float pB0 = ex2(sB[nt][0]);
            float pB1 = ex2(sB[nt][1]);
            float pB2 = ex2(sB[nt][2]);
            float pB3 = ex2(sB[nt][3]);
            lA0 += pA0 + pA1; lA1 += pA2 + pA3;
            lB0 += pB0 + pB1; lB1 += pB2 + pB3;
            int col = nt * 8 + 2 * t;
            *(float2*)&Ps[rA * AST + col]       = make_float2(to_tf32(pA0), to_tf32(pA1));
            *(float2*)&Ps[(rA + 8) * AST + col] = make_float2(to_tf32(pA2), to_tf32(pA3));
            *(float2*)&Ps[rB * AST + col]       = make_float2(to_tf32(pB0), to_tf32(pB1));
            *(float2*)&Ps[(rB + 8) * AST + col] = make_float2(to_tf32(pB2), to_tf32(pB3));
        }
        __syncwarp();

        // ---- O += P V  (both m-blocks share B fragments) ----
        const uint32_t* pu = (const uint32_t*)Ps;
        const uint32_t* vu = (const uint32_t*)Vs;
#pragma unroll
        for (int kt = 0; kt < 8; kt++) {
            uint32_t aA0 = pu[rA * AST + kt * 8 + t];
            uint32_t aA1 = pu[(rA + 8) * AST + kt * 8 + t];
            uint32_t aA2 = pu[rA * AST + kt * 8 + t + 4];
            uint32_t aA3 = pu[(rA + 8) * AST + kt * 8 + t + 4];
            uint32_t aB0 = pu[rB * AST + kt * 8 + t];
            uint32_t aB1 = pu[(rB + 8) * AST + kt * 8 + t];
            uint32_t aB2 = pu[rB * AST + kt * 8 + t + 4];
            uint32_t aB3 = pu[(rB + 8) * AST + kt * 8 + t + 4];
#pragma unroll
            for (int nt = 0; nt < 8; nt++) {
                uint32_t b0 = vu[(kt * 8 + t) * VST + nt * 8 + g];
                uint32_t b1 = vu[(kt * 8 + t + 4) * VST + nt * 8 + g];
                mma8(oA[nt], aA0, aA1, aA2, aA3, b0, b1);
                mma8(oB[nt], aB0, aB1, aB2, aB3, b0, b1);
            }
        }
    }

    // deferred l reduction over the 4 t-lanes of each row group
    lA0 += __shfl_xor_sync(0xffffffffu, lA0, 1);
    lA0 += __shfl_xor_sync(0xffffffffu, lA0, 2);
    lA1 += __shfl_xor_sync(0xffffffffu, lA1, 1);
    lA1 += __shfl_xor_sync(0xffffffffu, lA1, 2);
    lB0 += __shfl_xor_sync(0xffffffffu, lB0, 1);
    lB0 += __shfl_xor_sync(0xffffffffu, lB0, 2);
    lB1 += __shfl_xor_sync(0xffffffffu, lB1, 1);
    lB1 += __shfl_xor_sync(0xffffffffu, lB1, 2);
    float iA0 = 1.f / lA0, iA1 = 1.f / lA1, iB0 = 1.f / lB0, iB1 = 1.f / lB1;
#pragma unroll
    for (int nt = 0; nt < 8; nt++) {
        int col = nt * 8 + 2 * t;
        int r;
        r = m0 + rA;
        if (r < NTOK)
            *(float2*)(O + base + (size_t)r * HDIM + col) =
                make_float2(oA[nt][0] * iA0, oA[nt][1] * iA0);
        r = m0 + rA + 8;
        if (r < NTOK)
            *(float2*)(O + base + (size_t)r * HDIM + col) =
                make_float2(oA[nt][2] * iA1, oA[nt][3] * iA1);
        r = m0 + rB;
        if (r < NTOK)
            *(float2*)(O + base + (size_t)r * HDIM + col) =
                make_float2(oB[nt][0] * iB0, oB[nt][1] * iB0);
        r = m0 + rB + 8;
        if (r < NTOK)
            *(float2*)(O + base + (size_t)r * HDIM + col) =
                make_float2(oB[nt][2] * iB1, oB[nt][3] * iB1);
    }
}

// ---------------- qkv projection GEMM (tf32 tensor-core) --------------------
#define GST 36

__global__ __launch_bounds__(128) void qkv_tc(const float* __restrict__ x,
                                              const float* __restrict__ W) {
    __shared__ float As[64 * GST];
    __shared__ float Bs[64 * GST];
    int tid = threadIdx.x;
    int warp = tid >> 5, lane = tid & 31;
    int g = lane >> 2, t = lane & 3;
    int m0 = blockIdx.x * 64;
    int o0 = blockIdx.y * 64;
    int b = blockIdx.z;
    const int r0 = warp * 16 + g;

    float c[8][4];
#pragma unroll
    for (int nt = 0; nt < 8; nt++)
#pragma unroll
        for (int j = 0; j < 4; j++) c[nt][j] = 0.f;

    for (int c0 = 0; c0 < CDIM; c0 += 32) {
        __syncthreads();
#pragma unroll
        for (int e = 0; e < 4; e++) {
            int idx = tid + e * 128;
            int row = idx >> 3;
            int cs = (idx & 7) << 2;
            float4 a4 = make_float4(0.f, 0.f, 0.f, 0.f);
            if (m0 + row < NTOK)
                a4 = *(const float4*)(x + (size_t)(m0 + row) * (BATCH * CDIM) + b * CDIM + c0 + cs);
            float4 aw;
            aw.x = to_tf32(a4.x); aw.y = to_tf32(a4.y);
            aw.z = to_tf32(a4.z); aw.w = to_tf32(a4.w);
            *(float4*)&As[row * GST + cs] = aw;
            float4 b4 = *(const float4*)(W + (size_t)(o0 + row) * CDIM + c0 + cs);
            float4 bw;
            bw.x = to_tf32(b4.x); bw.y = to_tf32(b4.y);
            bw.z = to_tf32(b4.z); bw.w = to_tf32(b4.w);
            *(float4*)&Bs[row * GST + cs] = bw;
        }
        __syncthreads();

        const uint32_t* au = (const uint32_t*)As;
        const uint32_t* bu = (const uint32_t*)Bs;
#pragma unroll
        for (int kt = 0; kt < 4; kt++) {
            uint32_t a0 = au[r0 * GST + kt * 8 + t];
            uint32_t a1 = au[(r0 + 8) * GST + kt * 8 + t];
            uint32_t a2 = au[r0 * GST + kt * 8 + t + 4];
            uint32_t a3 = au[(r0 + 8) * GST + kt * 8 + t + 4];
#pragma unroll
            for (int nt = 0; nt < 8; nt++) {
                uint32_t b0 = bu[(nt * 8 + g) * GST + kt * 8 + t];
                uint32_t b1 = bu[(nt * 8 + g) * GST + kt * 8 + t + 4];
                mma8(c[nt], a0, a1, a2, a3, b0, b1);
            }
        }
    }

    int tsel = o0 / CDIM;
    int h = (o0 % CDIM) >> 6;
    float* dst = (tsel == 0) ? g_q : ((tsel == 1) ? g_k : g_v);
    dst += (size_t)((b * NHEAD + h) * NTOK) * HDIM;
    int gr0 = m0 + r0, gr1 = m0 + r0 + 8;
#pragma unroll
    for (int nt = 0; nt < 8; nt++) {
        int col = nt * 8 + 2 * t;
        if (gr0 < NTOK)
            *(float2*)&dst[(size_t)gr0 * HDIM + col] = make_float2(c[nt][0], c[nt][1]);
        if (gr1 < NTOK)
            *(float2*)&dst[(size_t)gr1 * HDIM + col] = make_float2(c[nt][2], c[nt][3]);
    }
}

// ---------------- output projection GEMM (tf32 TC; z-batched both outputs) --
// blockIdx.z encodes (which, b): which=0 -> x_ori from t1; which=1 -> x_out
// from t2 3-way sum with prescale 1/3.
__global__ __launch_bounds__(128) void proj_tc(const float* __restrict__ t1,
                                               const float* __restrict__ t2,
                                               const float* __restrict__ W,
                                               const float* __restrict__ bias,
                                               float* __restrict__ outbase) {
    __shared__ float As[64 * GST];
    __shared__ float Bs[64 * GST];
    int tid = threadIdx.x;
    int warp = tid >> 5, lane = tid & 31;
    int g = lane >> 2, t = lane & 3;
    int m0 = blockIdx.x * 64;
    int o0 = blockIdx.y * 64;
    int zb = blockIdx.z;
    int b = zb & 7;
    int which = zb >> 3;
    const float* s0 = which ? t2 : t1;
    const float* s1 = which ? (t2 + BHND) : nullptr;
    const float* s2 = which ? (t2 + 2 * BHND) : nullptr;
    float* out = which ? outbase : (outbase + NBC);
    float prescale = which ? (1.0f / 3.0f) : 1.0f;
    const int r0 = warp * 16 + g;

    float c[8][4];
#pragma unroll
    for (int nt = 0; nt < 8; nt++)
#pragma unroll
        for (int j = 0; j < 4; j++) c[nt][j] = 0.f;

    for (int c0 = 0; c0 < CDIM; c0 += 32) {
        int h = c0 >> 6;
        int dlo = c0 & 63;
        __syncthreads();
#pragma unroll
        for (int e = 0; e < 4; e++) {
            int idx = tid + e * 128;
            int row = idx >> 3;
            int cs = (idx & 7) << 2;
            float4 a4 = make_float4(0.f, 0.f, 0.f, 0.f);
            if (m0 + row < NTOK) {
                size_t off = (size_t)((b * NHEAD + h) * NTOK + m0 + row) * HDIM + dlo + cs;
                a4 = *(const float4*)(s0 + off);
                if (s1) {
                    float4 a1 = *(const float4*)(s1 + off);
                    float4 a2 = *(const float4*)(s2 + off);
                    a4.x += a1.x + a2.x; a4.y += a1.y + a2.y;
                    a4.z += a1.z + a2.z; a4.w += a1.w + a2.w;
                }
            }
            float4 aw;
            aw.x = to_tf32(a4.x); aw.y = to_tf32(a4.y);
            aw.z = to_tf32(a4.z); aw.w = to_tf32(a4.w);
            *(float4*)&As[row * GST + cs] = aw;
            float4 b4 = *(const float4*)(W + (size_t)(o0 + row) * CDIM + c0 + cs);
            float4 bw;
            bw.x = to_tf32(b4.x); bw.y = to_tf32(b4.y);
            bw.z = to_tf32(b4.z); bw.w = to_tf32(b4.w);
            *(float4*)&Bs[row * GST + cs] = bw;
        }
        __syncthreads();

        const uint32_t* au = (const uint32_t*)As;
        const uint32_t* bu = (const uint32_t*)Bs;
#pragma unroll
        for (int kt = 0; kt < 4; kt++) {
            uint32_t a0 = au[r0 * GST + kt * 8 + t];
            uint32_t a1 = au[(r0 + 8) * GST + kt * 8 + t];
            uint32_t a2 = au[r0 * GST + kt * 8 + t + 4];
            uint32_t a3 = au[(r0 + 8) * GST + kt * 8 + t + 4];
#pragma unroll
            for (int nt = 0; nt < 8; nt++) {
                uint32_t b0 = bu[(nt * 8 + g) * GST + kt * 8 + t];
                uint32_t b1 = bu[(nt * 8 + g) * GST + kt * 8 + t + 4];
                mma8(c[nt], a0, a1, a2, a3, b0, b1);
            }
        }
    }

    int gr0 = m0 + r0, gr1 = m0 + r0 + 8;
#pragma unroll
    for (int nt = 0; nt < 8; nt++) {
        int col = nt * 8 + 2 * t;
        float b0 = bias[o0 + col], b1 = bias[o0 + col + 1];
        if (gr0 < NTOK)
            *(float2*)(out + (size_t)gr0 * (BATCH * CDIM) + b * CDIM + o0 + col) =
                make_float2(c[nt][0] * prescale + b0, c[nt][1] * prescale + b1);
        if (gr1 < NTOK)
            *(float2*)(out + (size_t)gr1 * (BATCH * CDIM) + b * CDIM + o0 + col) =
                make_float2(c[nt][2] * prescale + b0, c[nt][3] * prescale + b1);
    }
}

// ---------------- host orchestration ---------------------------------------
extern "C" void kernel_launch(void* const* d_in, const int* in_sizes, int n_in,
                              void* d_out, int out_size) {
    const float* x = (const float*)d_in[0];
    const float* Wqkv = (const float*)d_in[1];
    const float* Wproj = (const float*)d_in[2];
    const float* bproj = (const float*)d_in[3];
    float* out = (float*)d_out;

    cudaFuncSetAttribute(attn_tc, cudaFuncAttributeMaxDynamicSharedMemorySize,
                         ATT_SMEM);

    float *q, *k, *v, *xs, *t1, *t2;
    cudaGetSymbolAddress((void**)&q, g_q);
    cudaGetSymbolAddress((void**)&k, g_k);
    cudaGetSymbolAddress((void**)&v, g_v);
    cudaGetSymbolAddress((void**)&xs, g_xs);
    cudaGetSymbolAddress((void**)&t1, g_t1);
    cudaGetSymbolAddress((void**)&t2, g_t2);

    const int LN3_GRID = (3 * BH * NTOK * 32 + 255) / 256;
    dim3 ga1((NTOK + 127) / 128, BH, 4);   // stage 0: ori + 3 branches
    dim3 ga2((NTOK + 127) / 128, BH, 3);   // stage 1: 3 branches
    dim3 gq((NTOK + 63) / 64, 36, BATCH);
    dim3 gp((NTOK + 63) / 64, 12, 2 * BATCH);  // both projections

    rownorm_kernel<<<(BATCH * NTOK * 32 + 255) / 256, 256>>>(x);
    invtemp_kernel<<<BATCH, 256>>>();

    qkv_tc<<<gq, 128>>>(x, Wqkv);

    // l2norm of v,k,q feeds the branch attns; then ONE launch runs
    // ori-attn (z=0) + 3 branch stage-1 attns (z=1..3)
    l2norm3_kernel<<<LN3_GRID, 256>>>(v, k, q, xs);
    attn_tc<<<ga1, 128, ATT_SMEM>>>(q, k, v, xs, t1, t2, 0);

    // re-normalize, branch stage-2 (z=0..2)
    l2norm3_kernel<<<LN3_GRID, 256>>>(t2, t2 + BHND, t2 + 2 * BHND, xs);
    attn_tc<<<ga2, 128, ATT_SMEM>>>(q, k, v, xs, t1, t2, 1);

    // both projections in one launch: x_ori from t1, x_out from summed t2
    proj_tc<<<gp, 128>>>(t1, t2, Wproj, bproj, out);
}

// round 16
// speedup vs baseline: 2.4841x; 1.5256x over previous
#include <cuda_runtime.h>
#include <cuda_fp16.h>
#include <math.h>
#include <stdint.h>
#include <string.h>

#define NTOK 1569
#define NTOKP 1600
#define BATCH 8
#define CDIM 768
#define NHEAD 12
#define HDIM 64
#define BH (BATCH*NHEAD)            /* 96 */
#define BHND (BH*NTOK*HDIM)         /* 9639936 */
#define NBC (NTOK*BATCH*CDIM)       /* 9639936 */
#define VTSZ (BH*HDIM*NTOKP)        /* 9830400 */

// ---------------- scratch (device globals: no allocation allowed) ----------
__device__ __half g_hq[BHND];
__device__ __half g_hk[BHND];
__device__ __half g_hv[BHND];
__device__ __half g_hvt[VTSZ];          // v transposed [bh][d][keyP]
__device__ __half g_hxs[3*BHND];        // l2norm outputs (key-major)
__device__ __half g_hxst[3*VTSZ];       // xs transposed (stage-1 V operand)
__device__ float g_t1[BHND];            // ori attention output (fp32)
__device__ float g_t2[3*BHND];          // branch outputs (fp32)
__device__ float g_rownorm[BATCH*NTOK];
__device__ float g_invtemp[BATCH];

// ---------------- helpers ---------------------------------------------------
__device__ __forceinline__ float to_tf32(float x) {
    uint32_t u;
    asm("cvt.rna.tf32.f32 %0, %1;" : "=r"(u) : "f"(x));
    return __uint_as_float(u);
}

__device__ __forceinline__ float ex2(float x) {
    float r;
    asm("ex2.approx.f32 %0, %1;" : "=f"(r) : "f"(x));
    return r;
}

__device__ __forceinline__ void mma8(float* c, uint32_t a0, uint32_t a1,
                                     uint32_t a2, uint32_t a3,
                                     uint32_t b0, uint32_t b1) {
    asm volatile(
        "mma.sync.aligned.m16n8k8.row.col.f32.tf32.tf32.f32 "
        "{%0,%1,%2,%3}, {%4,%5,%6,%7}, {%8,%9}, {%0,%1,%2,%3};"
        : "+f"(c[0]), "+f"(c[1]), "+f"(c[2]), "+f"(c[3])
        : "r"(a0), "r"(a1), "r"(a2), "r"(a3), "r"(b0), "r"(b1));
}

__device__ __forceinline__ void mma16(float* c, uint32_t a0, uint32_t a1,
                                      uint32_t a2, uint32_t a3,
                                      uint32_t b0, uint32_t b1) {
    asm volatile(
        "mma.sync.aligned.m16n8k16.row.col.f32.f16.f16.f32 "
        "{%0,%1,%2,%3}, {%4,%5,%6,%7}, {%8,%9}, {%0,%1,%2,%3};"
        : "+f"(c[0]), "+f"(c[1]), "+f"(c[2]), "+f"(c[3])
        : "r"(a0), "r"(a1), "r"(a2), "r"(a3), "r"(b0), "r"(b1));
}

__device__ __forceinline__ uint32_t h2u(__half2 h) {
    uint32_t u; memcpy(&u, &h, 4); return u;
}

// ---------------- per-token L2 norm over C (for inv_temp) ------------------
__global__ void rownorm_kernel(const float* __restrict__ x) {
    int r = (blockIdx.x * blockDim.x + threadIdx.x) >> 5;
    int lane = threadIdx.x & 31;
    if (r >= BATCH * NTOK) return;
    int b = r / NTOK, n = r - b * NTOK;
    const float* p = x + (size_t)n * (BATCH * CDIM) + b * CDIM;
    float ss = 0.f;
#pragma unroll
    for (int kblk = 0; kblk < 6; kblk++) {
        float4 v = *(const float4*)(p + kblk * 128 + lane * 4);
        ss += v.x * v.x + v.y * v.y + v.z * v.z + v.w * v.w;
    }
#pragma unroll
    for (int o = 16; o; o >>= 1) ss += __shfl_xor_sync(0xffffffffu, ss, o);
    if (lane == 0) g_rownorm[r] = sqrtf(ss);
}

__global__ void invtemp_kernel() {
    __shared__ float sh[256];
    int b = blockIdx.x;
    float s = 0.f;
    for (int n = threadIdx.x; n < NTOK; n += 256) s += g_rownorm[b * NTOK + n];
    sh[threadIdx.x] = s;
    __syncthreads();
    for (int o = 128; o; o >>= 1) {
        if (threadIdx.x < o) sh[threadIdx.x] += sh[threadIdx.x + o];
        __syncthreads();
    }
    if (threadIdx.x == 0) g_invtemp[b] = (sh[0] / (float)NTOK) * 0.125f;
}

// ---------------- batched l2 normalize: half in -> half out -----------------
__global__ void l2norm3_h(const __half* __restrict__ p0,
                          const __half* __restrict__ p1,
                          const __half* __restrict__ p2,
                          __half* __restrict__ out) {
    int r = (blockIdx.x * blockDim.x + threadIdx.x) >> 5;
    int lane = threadIdx.x & 31;
    if (r >= 3 * BH * NTOK) return;
    int z = r / (BH * NTOK);
    int rr = r - z * (BH * NTOK);
    const __half* in = (z == 0) ? p0 : ((z == 1) ? p1 : p2);
    __half2 h = *(const __half2*)(in + (size_t)rr * HDIM + lane * 2);
    float2 v = __half22float2(h);
    float ss = v.x * v.x + v.y * v.y;
#pragma unroll
    for (int o = 16; o; o >>= 1) ss += __shfl_xor_sync(0xffffffffu, ss, o);
    float inv = 1.f / fmaxf(sqrtf(ss), 1e-12f);
    *(__half2*)(out + (size_t)r * HDIM + lane * 2) =
        __floats2half2_rn(v.x * inv, v.y * inv);
}

// ---------------- batched l2 normalize: float in (t2) -> half out -----------
__global__ void l2norm3_f(const float* __restrict__ in, __half* __restrict__ out) {
    int r = (blockIdx.x * blockDim.x + threadIdx.x) >> 5;
    int lane = threadIdx.x & 31;
    if (r >= 3 * BH * NTOK) return;
    float2 v = *(const float2*)(in + (size_t)r * HDIM + lane * 2);
    float ss = v.x * v.x + v.y * v.y;
#pragma unroll
    for (int o = 16; o; o >>= 1) ss += __shfl_xor_sync(0xffffffffu, ss, o);
    float inv = 1.f / fmaxf(sqrtf(ss), 1e-12f);
    *(__half2*)(out + (size_t)r * HDIM + lane * 2) =
        __floats2half2_rn(v.x * inv, v.y * inv);
}

// ---------------- transpose [S][key NTOK][64] -> [S][64][NTOKP] -------------
__global__ void transpose_kernel(const __half* __restrict__ src,
                                 __half* __restrict__ dst) {
    __shared__ uint32_t tile[64][33];   // [key][dpair]
    int tid = threadIdx.x;
    int kt0 = blockIdx.x * 64;
    size_t sbase = (size_t)blockIdx.y * NTOK * HDIM;
    size_t dbase = (size_t)blockIdx.y * HDIM * NTOKP;
#pragma unroll
    for (int e = 0; e < 4; e++) {
        int idx = tid + e * 128;
        int key = idx >> 3, c8 = idx & 7;
        uint4 v = make_uint4(0, 0, 0, 0);
        if (kt0 + key < NTOK)
            v = *(const uint4*)(src + sbase + (size_t)(kt0 + key) * HDIM + c8 * 8);
        tile[key][c8 * 4 + 0] = v.x; tile[key][c8 * 4 + 1] = v.y;
        tile[key][c8 * 4 + 2] = v.z; tile[key][c8 * 4 + 3] = v.w;
    }
    __syncthreads();
    const __half* th = (const __half*)tile;   // row stride 66 halves
#pragma unroll
    for (int e = 0; e < 4; e++) {
        int idx = tid + e * 128;
        int d = idx >> 3, kc = idx & 7;
        uint32_t o[4];
#pragma unroll
        for (int m = 0; m < 4; m++) {
            __half lo = th[(kc * 8 + 2 * m) * 66 + d];
            __half hi = th[(kc * 8 + 2 * m + 1) * 66 + d];
            o[m] = h2u(__halves2half2(lo, hi));
        }
        *(uint4*)(dst + dbase + (size_t)d * NTOKP + kt0 + kc * 8) = *(uint4*)o;
    }
}

// ---------------- flash attention (fp16 m16n8k16, M=32/warp) ----------------
// Q/K key-major half [key][64]; V transposed half [d][keyP]. P half2 in smem.
// u32 strides 36 everywhere: fragment-read bank = 4g+t permutation.
#define ST2 36
#define ATT_SMEM ((128*ST2 + 64*ST2 + 64*ST2) * 4)

__global__ __launch_bounds__(128) void attn_tc(
    const __half* __restrict__ hq, const __half* __restrict__ hk,
    const __half* __restrict__ hvt, const __half* __restrict__ hxs,
    const __half* __restrict__ hxst,
    float* __restrict__ t1, float* __restrict__ t2, int stage) {
    extern __shared__ float smf[];
    uint32_t* Ps2 = (uint32_t*)smf;            // 128 x ST2 (Q staging, then P)
    uint32_t* Ks2 = Ps2 + 128 * ST2;           // 64 x ST2
    uint32_t* Vs2 = Ks2 + 64 * ST2;            // 64 x ST2

    // ---- per-z operand selection ----
    const __half *Q, *K, *V;
    float* O;
    int useInvTemp;
    int z = blockIdx.z;
    if (stage == 0) {
        if (z == 0) { Q = hq; K = hk; V = hvt; O = t1; useInvTemp = 0; }
        else {
            const __half* p = hxs + (size_t)(z - 1) * BHND;
            Q = p; K = p;
            V = hxst + (size_t)(z - 1) * VTSZ;
            O = t2 + (size_t)(z - 1) * BHND;
            useInvTemp = 1;
        }
    } else {
        const __half* p = hxs + (size_t)z * BHND;
        Q = p; K = p; V = hvt;
        O = t2 + (size_t)z * BHND;
        useInvTemp = 1;
    }

    int tid = threadIdx.x;
    int warp = tid >> 5, lane = tid & 31;
    int g = lane >> 2, t = lane & 3;
    int bh = blockIdx.y;
    int m0 = blockIdx.x * 128;
    float scale = useInvTemp ? g_invtemp[bh / NHEAD] : 0.125f;
    const float qscale = scale * 1.4426950408889634f;
    const size_t baseQ = (size_t)bh * NTOK * HDIM;
    const size_t baseV = (size_t)bh * HDIM * NTOKP;
    const int rA = warp * 32 + g;
    const int rB = warp * 32 + 16 + g;

    // ---- stage Q (scaled, half) into Ps2 ----
#pragma unroll
    for (int e = 0; e < 8; e++) {
        int idx = tid + e * 128;
        int row = idx >> 3, c8 = idx & 7;
        uint4 v = make_uint4(0, 0, 0, 0);
        if (m0 + row < NTOK)
            v = *(const uint4*)(Q + baseQ + (size_t)(m0 + row) * HDIM + c8 * 8);
        uint32_t* pr = (uint32_t*)&v;
        uint32_t o[4];
#pragma unroll
        for (int i = 0; i < 4; i++) {
            __half2 h; memcpy(&h, &pr[i], 4);
            float2 f = __half22float2(h);
            o[i] = h2u(__floats2half2_rn(f.x * qscale, f.y * qscale));
        }
        Ps2[row * ST2 + c8 * 4 + 0] = o[0];
        Ps2[row * ST2 + c8 * 4 + 1] = o[1];
        Ps2[row * ST2 + c8 * 4 + 2] = o[2];
        Ps2[row * ST2 + c8 * 4 + 3] = o[3];
    }
    __syncthreads();

    // ---- hoist Q fragments (4 k16-chunks) ----
    uint32_t qA[4][4], qB[4][4];
#pragma unroll
    for (int kt = 0; kt < 4; kt++) {
        qA[kt][0] = Ps2[rA * ST2 + kt * 8 + t];
        qA[kt][1] = Ps2[(rA + 8) * ST2 + kt * 8 + t];
        qA[kt][2] = Ps2[rA * ST2 + kt * 8 + t + 4];
        qA[kt][3] = Ps2[(rA + 8) * ST2 + kt * 8 + t + 4];
        qB[kt][0] = Ps2[rB * ST2 + kt * 8 + t];
        qB[kt][1] = Ps2[(rB + 8) * ST2 + kt * 8 + t];
        qB[kt][2] = Ps2[rB * ST2 + kt * 8 + t + 4];
        qB[kt][3] = Ps2[(rB + 8) * ST2 + kt * 8 + t + 4];
    }

    float lA0 = 0.f, lA1 = 0.f, lB0 = 0.f, lB1 = 0.f;
    float oA[8][4], oB[8][4];
#pragma unroll
    for (int nt = 0; nt < 8; nt++)
#pragma unroll
        for (int j = 0; j < 4; j++) { oA[nt][j] = 0.f; oB[nt][j] = 0.f; }

    for (int kt0 = 0; kt0 < NTOK; kt0 += 64) {
        __syncthreads();
        // ---- stage K (key-major) + V (d-major) tiles ----
#pragma unroll
        for (int e = 0; e < 4; e++) {
            int idx = tid + e * 128;
            int row = idx >> 3, c8 = idx & 7;
            uint4 kv = make_uint4(0, 0, 0, 0);
            if (kt0 + row < NTOK)
                kv = *(const uint4*)(K + baseQ + (size_t)(kt0 + row) * HDIM + c8 * 8);
            Ks2[row * ST2 + c8 * 4 + 0] = kv.x;
            Ks2[row * ST2 + c8 * 4 + 1] = kv.y;
            Ks2[row * ST2 + c8 * 4 + 2] = kv.z;
            Ks2[row * ST2 + c8 * 4 + 3] = kv.w;
            // V: row -> d, c8 -> keypair group (always in-bounds, pad is zero)
            uint4 vv = *(const uint4*)(V + baseV + (size_t)row * NTOKP + kt0 + c8 * 8);
            Vs2[row * ST2 + c8 * 4 + 0] = vv.x;
            Vs2[row * ST2 + c8 * 4 + 1] = vv.y;
            Vs2[row * ST2 + c8 * 4 + 2] = vv.z;
            Vs2[row * ST2 + c8 * 4 + 3] = vv.w;
        }
        __syncthreads();

        // ---- S = (Q*qscale) K^T ----
        float sA[8][4], sB[8][4];
#pragma unroll
        for (int nt = 0; nt < 8; nt++)
#pragma unroll
            for (int j = 0; j < 4; j++) { sA[nt][j] = 0.f; sB[nt][j] = 0.f; }

#pragma unroll
        for (int kt = 0; kt < 4; kt++) {
#pragma unroll
            for (int nt = 0; nt < 8; nt++) {
                uint32_t b0 = Ks2[(nt * 8 + g) * ST2 + kt * 8 + t];
                uint32_t b1 = Ks2[(nt * 8 + g) * ST2 + kt * 8 + t + 4];
                mma16(sA[nt], qA[kt][0], qA[kt][1], qA[kt][2], qA[kt][3], b0, b1);
                mma16(sB[nt], qB[kt][0], qB[kt][1], qB[kt][2], qB[kt][3], b0, b1);
            }
        }

        // ---- no-max softmax: p = 2^s ----
        bool tail = (kt0 + 64 > NTOK);
#pragma unroll
        for (int nt = 0; nt < 8; nt++) {
            if (tail) {
                int cg = kt0 + nt * 8 + 2 * t;
                if (cg >= NTOK) {
                    sA[nt][0] = -1e30f; sA[nt][2] = -1e30f;
                    sB[nt][0] = -1e30f; sB[nt][2] = -1e30f;
                }
                if (cg + 1 >= NTOK) {
                    sA[nt][1] = -1e30f; sA[nt][3] = -1e30f;
                    sB[nt][1] = -1e30f; sB[nt][3] = -1e30f;
                }
            }
            float pA0 = ex2(sA[nt][0]);
            float pA1 = ex2(sA[nt][1]);
            float pA2 = ex2(sA[nt][2]);
            float pA3 = ex2(sA[nt][3]);
            float pB0 = ex2(sB[nt][0]);
            float pB1 = ex2(sB[nt][1]);
            float pB2 = ex2(sB[nt][2]);
            float pB3 = ex2(sB[nt][3]);
            lA0 += pA0 + pA1; lA1 += pA2 + pA3;
            lB0 += pB0 + pB1; lB1 += pB2 + pB3;
            int kp = nt * 4 + t;   // keypair column
            Ps2[rA * ST2 + kp]       = h2u(__floats2half2_rn(pA0, pA1));
            Ps2[(rA + 8) * ST2 + kp] = h2u(__floats2half2_rn(pA2, pA3));
            Ps2[rB * ST2 + kp]       = h2u(__floats2half2_rn(pB0, pB1));
            Ps2[(rB + 8) * ST2 + kp] = h2u(__floats2half2_rn(pB2, pB3));
        }
        __syncwarp();

        // ---- O += P V ----
#pragma unroll
        for (int kt = 0; kt < 4; kt++) {
            uint32_t aA0 = Ps2[rA * ST2 + kt * 8 + t];
            uint32_t aA1 = Ps2[(rA + 8) * ST2 + kt * 8 + t];
            uint32_t aA2 = Ps2[rA * ST2 + kt * 8 + t + 4];
            uint32_t aA3 = Ps2[(rA + 8) * ST2 + kt * 8 + t + 4];
            uint32_t aB0 = Ps2[rB * ST2 + kt * 8 + t];
            uint32_t aB1 = Ps2[(rB + 8) * ST2 + kt * 8 + t];
            uint32_t aB2 = Ps2[rB * ST2 + kt * 8 + t + 4];
            uint32_t aB3 = Ps2[(rB + 8) * ST2 + kt * 8 + t + 4];
#pragma unroll
            for (int nt = 0; nt < 8; nt++) {
                uint32_t b0 = Vs2[(nt * 8 + g) * ST2 + kt * 8 + t];
                uint32_t b1 = Vs2[(nt * 8 + g) * ST2 + kt * 8 + t + 4];
                mma16(oA[nt], aA0, aA1, aA2, aA3, b0, b1);
                mma16(oB[nt], aB0, aB1, aB2, aB3, b0, b1);
            }
        }
    }

    // deferred l reduction over the 4 t-lanes of each row group
    lA0 += __shfl_xor_sync(0xffffffffu, lA0, 1);
    lA0 += __shfl_xor_sync(0xffffffffu, lA0, 2);
    lA1 += __shfl_xor_sync(0xffffffffu, lA1, 1);
    lA1 += __shfl_xor_sync(0xffffffffu, lA1, 2);
    lB0 += __shfl_xor_sync(0xffffffffu, lB0, 1);
    lB0 += __shfl_xor_sync(0xffffffffu, lB0, 2);
    lB1 += __shfl_xor_sync(0xffffffffu, lB1, 1);
    lB1 += __shfl_xor_sync(0xffffffffu, lB1, 2);
    float iA0 = 1.f / lA0, iA1 = 1.f / lA1, iB0 = 1.f / lB0, iB1 = 1.f / lB1;
    const size_t baseO = (size_t)bh * NTOK * HDIM;
#pragma unroll
    for (int nt = 0; nt < 8; nt++) {
        int col = nt * 8 + 2 * t;
        int r;
        r = m0 + rA;
        if (r < NTOK)
            *(float2*)(O + baseO + (size_t)r * HDIM + col) =
                make_float2(oA[nt][0] * iA0, oA[nt][1] * iA0);
        r = m0 + rA + 8;
        if (r < NTOK)
            *(float2*)(O + baseO + (size_t)r * HDIM + col) =
                make_float2(oA[nt][2] * iA1, oA[nt][3] * iA1);
        r = m0 + rB;
        if (r < NTOK)
            *(float2*)(O + baseO + (size_t)r * HDIM + col) =
                make_float2(oB[nt][0] * iB0, oB[nt][1] * iB0);
        r = m0 + rB + 8;
        if (r < NTOK)
            *(float2*)(O + baseO + (size_t)r * HDIM + col) =
                make_float2(oB[nt][2] * iB1, oB[nt][3] * iB1);
    }
}

// ---------------- qkv projection GEMM (tf32 TC, half outputs) ---------------
#define GST 36

__global__ __launch_bounds__(128) void qkv_tc(const float* __restrict__ x,
                                              const float* __restrict__ W) {
    __shared__ float As[64 * GST];
    __shared__ float Bs[64 * GST];
    int tid = threadIdx.x;
    int warp = tid >> 5, lane = tid & 31;
    int g = lane >> 2, t = lane & 3;
    int m0 = blockIdx.x * 64;
    int o0 = blockIdx.y * 64;
    int b = blockIdx.z;
    const int r0 = warp * 16 + g;

    float c[8][4];
#pragma unroll
    for (int nt = 0; nt < 8; nt++)
#pragma unroll
        for (int j = 0; j < 4; j++) c[nt][j] = 0.f;

    for (int c0 = 0; c0 < CDIM; c0 += 32) {
        __syncthreads();
#pragma unroll
        for (int e = 0; e < 4; e++) {
            int idx = tid + e * 128;
            int row = idx >> 3;
            int cs = (idx & 7) << 2;
            float4 a4 = make_float4(0.f, 0.f, 0.f, 0.f);
            if (m0 + row < NTOK)
                a4 = *(const float4*)(x + (size_t)(m0 + row) * (BATCH * CDIM) + b * CDIM + c0 + cs);
            float4 aw;
            aw.x = to_tf32(a4.x); aw.y = to_tf32(a4.y);
            aw.z = to_tf32(a4.z); aw.w = to_tf32(a4.w);
            *(float4*)&As[row * GST + cs] = aw;
            float4 b4 = *(const float4*)(W + (size_t)(o0 + row) * CDIM + c0 + cs);
            float4 bw;
            bw.x = to_tf32(b4.x); bw.y = to_tf32(b4.y);
            bw.z = to_tf32(b4.z); bw.w = to_tf32(b4.w);
            *(float4*)&Bs[row * GST + cs] = bw;
        }
        __syncthreads();

        const uint32_t* au = (const uint32_t*)As;
        const uint32_t* bu = (const uint32_t*)Bs;
#pragma unroll
        for (int kt = 0; kt < 4; kt++) {
            uint32_t a0 = au[r0 * GST + kt * 8 + t];
            uint32_t a1 = au[(r0 + 8) * GST + kt * 8 + t];
            uint32_t a2 = au[r0 * GST + kt * 8 + t + 4];
            uint32_t a3 = au[(r0 + 8) * GST + kt * 8 + t + 4];
#pragma unroll
            for (int nt = 0; nt < 8; nt++) {
                uint32_t b0 = bu[(nt * 8 + g) * GST + kt * 8 + t];
                uint32_t b1 = bu[(nt * 8 + g) * GST + kt * 8 + t + 4];
                mma8(c[nt], a0, a1, a2, a3, b0, b1);
            }
        }
    }

    int tsel = o0 / CDIM;
    int h = (o0 % CDIM) >> 6;
    __half* dst = (tsel == 0) ? g_hq : ((tsel == 1) ? g_hk : g_hv);
    dst += (size_t)((b * NHEAD + h) * NTOK) * HDIM;
    int gr0 = m0 + r0, gr1 = m0 + r0 + 8;
#pragma unroll
    for (int nt = 0; nt < 8; nt++) {
        int col = nt * 8 + 2 * t;
        if (gr0 < NTOK)
            *(__half2*)&dst[(size_t)gr0 * HDIM + col] =
                __floats2half2_rn(c[nt][0], c[nt][1]);
        if (gr1 < NTOK)
            *(__half2*)&dst[(size_t)gr1 * HDIM + col] =
                __floats2half2_rn(c[nt][2], c[nt][3]);
    }
}

// ---------------- output projection GEMM (tf32 TC; z-batched both outputs) --
__global__ __launch_bounds__(128) void proj_tc(const float* __restrict__ t1,
                                               const float* __restrict__ t2,
                                               const float* __restrict__ W,
                                               const float* __restrict__ bias,
                                               float* __restrict__ outbase) {
    __shared__ float As[64 * GST];
    __shared__ float Bs[64 * GST];
    int tid = threadIdx.x;
    int warp = tid >> 5, lane = tid & 31;
    int g = lane >> 2, t = lane & 3;
    int m0 = blockIdx.x * 64;
    int o0 = blockIdx.y * 64;
    int zb = blockIdx.z;
    int b = zb & 7;
    int which = zb >> 3;
    const float* s0 = which ? t2 : t1;
    const float* s1 = which ? (t2 + BHND) : nullptr;
    const float* s2 = which ? (t2 + 2 * BHND) : nullptr;
    float* out = which ? outbase : (outbase + NBC);
    float prescale = which ? (1.0f / 3.0f) : 1.0f;
    const int r0 = warp * 16 + g;

    float c[8][4];
#pragma unroll
    for (int nt = 0; nt < 8; nt++)
#pragma unroll
        for (int j = 0; j < 4; j++) c[nt][j] = 0.f;

    for (int c0 = 0; c0 < CDIM; c0 += 32) {
        int h = c0 >> 6;
        int dlo = c0 & 63;
        __syncthreads();
#pragma unroll
        for (int e = 0; e < 4; e++) {
            int idx = tid + e * 128;
            int row = idx >> 3;
            int cs = (idx & 7) << 2;
            float4 a4 = make_float4(0.f, 0.f, 0.f, 0.f);
            if (m0 + row < NTOK) {
                size_t off = (size_t)((b * NHEAD + h) * NTOK + m0 + row) * HDIM + dlo + cs;
                a4 = *(const float4*)(s0 + off);
                if (s1) {
                    float4 a1 = *(const float4*)(s1 + off);
                    float4 a2 = *(const float4*)(s2 + off);
                    a4.x += a1.x + a2.x; a4.y += a1.y + a2.y;
                    a4.z += a1.z + a2.z; a4.w += a1.w + a2.w;
                }
            }
            float4 aw;
            aw.x = to_tf32(a4.x); aw.y = to_tf32(a4.y);
            aw.z = to_tf32(a4.z); aw.w = to_tf32(a4.w);
            *(float4*)&As[row * GST + cs] = aw;
            float4 b4 = *(const float4*)(W + (size_t)(o0 + row) * CDIM + c0 + cs);
            float4 bw;
            bw.x = to_tf32(b4.x); bw.y = to_tf32(b4.y);
            bw.z = to_tf32(b4.z); bw.w = to_tf32(b4.w);
            *(float4*)&Bs[row * GST + cs] = bw;
        }
        __syncthreads();

        const uint32_t* au = (const uint32_t*)As;
        const uint32_t* bu = (const uint32_t*)Bs;
#pragma unroll
        for (int kt = 0; kt < 4; kt++) {
            uint32_t a0 = au[r0 * GST + kt * 8 + t];
            uint32_t a1 = au[(r0 + 8) * GST + kt * 8 + t];
            uint32_t a2 = au[r0 * GST + kt * 8 + t + 4];
            uint32_t a3 = au[(r0 + 8) * GST + kt * 8 + t + 4];
#pragma unroll
            for (int nt = 0; nt < 8; nt++) {
                uint32_t b0 = bu[(nt * 8 + g) * GST + kt * 8 + t];
                uint32_t b1 = bu[(nt * 8 + g) * GST + kt * 8 + t + 4];
                mma8(c[nt], a0, a1, a2, a3, b0, b1);
            }
        }
    }

    int gr0 = m0 + r0, gr1 = m0 + r0 + 8;
#pragma unroll
    for (int nt = 0; nt < 8; nt++) {
        int col = nt * 8 + 2 * t;
        float b0 = bias[o0 + col], b1 = bias[o0 + col + 1];
        if (gr0 < NTOK)
            *(float2*)(out + (size_t)gr0 * (BATCH * CDIM) + b * CDIM + o0 + col) =
                make_float2(c[nt][0] * prescale + b0, c[nt][1] * prescale + b1);
        if (gr1 < NTOK)
            *(float2*)(out + (size_t)gr1 * (BATCH * CDIM) + b * CDIM + o0 + col) =
                make_float2(c[nt][2] * prescale + b0, c[nt][3] * prescale + b1);
    }
}

// ---------------- host orchestration ---------------------------------------
extern "C" void kernel_launch(void* const* d_in, const int* in_sizes, int n_in,
                              void* d_out, int out_size) {
    const float* x = (const float*)d_in[0];
    const float* Wqkv = (const float*)d_in[1];
    const float* Wproj = (const float*)d_in[2];
    const float* bproj = (const float*)d_in[3];
    float* out = (float*)d_out;

    cudaFuncSetAttribute(attn_tc, cudaFuncAttributeMaxDynamicSharedMemorySize,
                         ATT_SMEM);

    __half *hq, *hk, *hv, *hvt, *hxs, *hxst;
    float *t1, *t2;
    cudaGetSymbolAddress((void**)&hq, g_hq);
    cudaGetSymbolAddress((void**)&hk, g_hk);
    cudaGetSymbolAddress((void**)&hv, g_hv);
    cudaGetSymbolAddress((void**)&hvt, g_hvt);
    cudaGetSymbolAddress((void**)&hxs, g_hxs);
    cudaGetSymbolAddress((void**)&hxst, g_hxst);
    cudaGetSymbolAddress((void**)&t1, g_t1);
    cudaGetSymbolAddress((void**)&t2, g_t2);

    const int LN3_GRID = (3 * BH * NTOK * 32 + 255) / 256;
    dim3 ga1((NTOK + 127) / 128, BH, 4);   // stage 0: ori + 3 branches
    dim3 ga2((NTOK + 127) / 128, BH, 3);   // stage 1: 3 branches
    dim3 gq((NTOK + 63) / 64, 36, BATCH);
    dim3 gp((NTOK + 63) / 64, 12, 2 * BATCH);
    dim3 gtv(NTOKP / 64, BH);              // transpose v
    dim3 gtx(NTOKP / 64, 3 * BH);          // transpose xs

    rownorm_kernel<<<(BATCH * NTOK * 32 + 255) / 256, 256>>>(x);
    invtemp_kernel<<<BATCH, 256>>>();

    qkv_tc<<<gq, 128>>>(x, Wqkv);

    // v -> vt; l2norm(v,k,q) -> xs; xs -> xst
    transpose_kernel<<<gtv, 128>>>(hv, hvt);
    l2norm3_h<<<LN3_GRID, 256>>>(hv, hk, hq, hxs);
    transpose_kernel<<<gtx, 128>>>(hxs, hxst);

    // stage 0: ori-attn (z=0) + 3 branch stage-1 attns (z=1..3)
    attn_tc<<<ga1, 128, ATT_SMEM>>>(hq, hk, hvt, hxs, hxst, t1, t2, 0);

    // re-normalize branch outputs, stage 1 (z=0..2), V = vt
    l2norm3_f<<<LN3_GRID, 256>>>(t2, hxs);
    attn_tc<<<ga2, 128, ATT_SMEM>>>(hq, hk, hvt, hxs, hxst, t1, t2, 1);

    // both projections in one launch: x_ori from t1, x_out from summed t2
    proj_tc<<<gp, 128>>>(t1, t2, Wproj, bproj, out);
}

// round 17
// speedup vs baseline: 2.5575x; 1.0295x over previous
#include <cuda_runtime.h>
#include <cuda_fp16.h>
#include <math.h>
#include <stdint.h>
#include <string.h>

#define NTOK 1569
#define NTOKP 1600
#define BATCH 8
#define CDIM 768
#define NHEAD 12
#define HDIM 64
#define BH (BATCH*NHEAD)            /* 96 */
#define BHND (BH*NTOK*HDIM)         /* 9639936 */
#define NBC (NTOK*BATCH*CDIM)       /* 9639936 */
#define VTSZ (BH*HDIM*NTOKP)        /* 9830400 */

// ---------------- scratch (device globals: no allocation allowed) ----------
__device__ __half g_hq[BHND];
__device__ __half g_hk[BHND];
__device__ __half g_hv[BHND];
__device__ __half g_hvt[VTSZ];          // v transposed [bh][d][keyP]
__device__ __half g_hxs[3*BHND];        // l2norm outputs (key-major)
__device__ __half g_hxst[3*VTSZ];       // xs transposed (stage-1 V operand)
__device__ float g_t1[BHND];            // ori attention output (fp32)
__device__ float g_t2[3*BHND];          // branch outputs (fp32)
__device__ float g_rownorm[BATCH*NTOK];
__device__ float g_invtemp[BATCH];

// ---------------- helpers ---------------------------------------------------
__device__ __forceinline__ float ex2(float x) {
    float r;
    asm("ex2.approx.f32 %0, %1;" : "=f"(r) : "f"(x));
    return r;
}

__device__ __forceinline__ void mma16(float* c, uint32_t a0, uint32_t a1,
                                      uint32_t a2, uint32_t a3,
                                      uint32_t b0, uint32_t b1) {
    asm volatile(
        "mma.sync.aligned.m16n8k16.row.col.f32.f16.f16.f32 "
        "{%0,%1,%2,%3}, {%4,%5,%6,%7}, {%8,%9}, {%0,%1,%2,%3};"
        : "+f"(c[0]), "+f"(c[1]), "+f"(c[2]), "+f"(c[3])
        : "r"(a0), "r"(a1), "r"(a2), "r"(a3), "r"(b0), "r"(b1));
}

__device__ __forceinline__ uint32_t h2u(__half2 h) {
    uint32_t u; memcpy(&u, &h, 4); return u;
}

// ---------------- per-token L2 norm over C (for inv_temp) ------------------
__global__ void rownorm_kernel(const float* __restrict__ x) {
    int r = (blockIdx.x * blockDim.x + threadIdx.x) >> 5;
    int lane = threadIdx.x & 31;
    if (r >= BATCH * NTOK) return;
    int b = r / NTOK, n = r - b * NTOK;
    const float* p = x + (size_t)n * (BATCH * CDIM) + b * CDIM;
    float ss = 0.f;
#pragma unroll
    for (int kblk = 0; kblk < 6; kblk++) {
        float4 v = *(const float4*)(p + kblk * 128 + lane * 4);
        ss += v.x * v.x + v.y * v.y + v.z * v.z + v.w * v.w;
    }
#pragma unroll
    for (int o = 16; o; o >>= 1) ss += __shfl_xor_sync(0xffffffffu, ss, o);
    if (lane == 0) g_rownorm[r] = sqrtf(ss);
}

__global__ void invtemp_kernel() {
    __shared__ float sh[256];
    int b = blockIdx.x;
    float s = 0.f;
    for (int n = threadIdx.x; n < NTOK; n += 256) s += g_rownorm[b * NTOK + n];
    sh[threadIdx.x] = s;
    __syncthreads();
    for (int o = 128; o; o >>= 1) {
        if (threadIdx.x < o) sh[threadIdx.x] += sh[threadIdx.x + o];
        __syncthreads();
    }
    if (threadIdx.x == 0) g_invtemp[b] = (sh[0] / (float)NTOK) * 0.125f;
}

// ---------------- batched l2 normalize: half in -> half out -----------------
__global__ void l2norm3_h(const __half* __restrict__ p0,
                          const __half* __restrict__ p1,
                          const __half* __restrict__ p2,
                          __half* __restrict__ out) {
    int r = (blockIdx.x * blockDim.x + threadIdx.x) >> 5;
    int lane = threadIdx.x & 31;
    if (r >= 3 * BH * NTOK) return;
    int z = r / (BH * NTOK);
    int rr = r - z * (BH * NTOK);
    const __half* in = (z == 0) ? p0 : ((z == 1) ? p1 : p2);
    __half2 h = *(const __half2*)(in + (size_t)rr * HDIM + lane * 2);
    float2 v = __half22float2(h);
    float ss = v.x * v.x + v.y * v.y;
#pragma unroll
    for (int o = 16; o; o >>= 1) ss += __shfl_xor_sync(0xffffffffu, ss, o);
    float inv = 1.f / fmaxf(sqrtf(ss), 1e-12f);
    *(__half2*)(out + (size_t)r * HDIM + lane * 2) =
        __floats2half2_rn(v.x * inv, v.y * inv);
}

// ---------------- batched l2 normalize: float in (t2) -> half out -----------
__global__ void l2norm3_f(const float* __restrict__ in, __half* __restrict__ out) {
    int r = (blockIdx.x * blockDim.x + threadIdx.x) >> 5;
    int lane = threadIdx.x & 31;
    if (r >= 3 * BH * NTOK) return;
    float2 v = *(const float2*)(in + (size_t)r * HDIM + lane * 2);
    float ss = v.x * v.x + v.y * v.y;
#pragma unroll
    for (int o = 16; o; o >>= 1) ss += __shfl_xor_sync(0xffffffffu, ss, o);
    float inv = 1.f / fmaxf(sqrtf(ss), 1e-12f);
    *(__half2*)(out + (size_t)r * HDIM + lane * 2) =
        __floats2half2_rn(v.x * inv, v.y * inv);
}

// ---------------- transpose [S][key NTOK][64] -> [S][64][NTOKP] -------------
__global__ void transpose_kernel(const __half* __restrict__ src,
                                 __half* __restrict__ dst) {
    __shared__ uint32_t tile[64][33];   // [key][dpair]
    int tid = threadIdx.x;
    int kt0 = blockIdx.x * 64;
    size_t sbase = (size_t)blockIdx.y * NTOK * HDIM;
    size_t dbase = (size_t)blockIdx.y * HDIM * NTOKP;
#pragma unroll
    for (int e = 0; e < 4; e++) {
        int idx = tid + e * 128;
        int key = idx >> 3, c8 = idx & 7;
        uint4 v = make_uint4(0, 0, 0, 0);
        if (kt0 + key < NTOK)
            v = *(const uint4*)(src + sbase + (size_t)(kt0 + key) * HDIM + c8 * 8);
        tile[key][c8 * 4 + 0] = v.x; tile[key][c8 * 4 + 1] = v.y;
        tile[key][c8 * 4 + 2] = v.z; tile[key][c8 * 4 + 3] = v.w;
    }
    __syncthreads();
    const __half* th = (const __half*)tile;   // row stride 66 halves
#pragma unroll
    for (int e = 0; e < 4; e++) {
        int idx = tid + e * 128;
        int d = idx >> 3, kc = idx & 7;
        uint32_t o[4];
#pragma unroll
        for (int m = 0; m < 4; m++) {
            __half lo = th[(kc * 8 + 2 * m) * 66 + d];
            __half hi = th[(kc * 8 + 2 * m + 1) * 66 + d];
            o[m] = h2u(__halves2half2(lo, hi));
        }
        *(uint4*)(dst + dbase + (size_t)d * NTOKP + kt0 + kc * 8) = *(uint4*)o;
    }
}

// ---------------- flash attention (fp16 m16n8k16, M=32/warp) ----------------
// Q/K key-major half [key][64]; V transposed half [d][keyP]. P half2 in smem.
// u32 strides 36 everywhere: fragment-read bank = 4g+t permutation.
#define ST2 36
#define ATT_SMEM ((128*ST2 + 64*ST2 + 64*ST2) * 4)

__global__ __launch_bounds__(128) void attn_tc(
    const __half* __restrict__ hq, const __half* __restrict__ hk,
    const __half* __restrict__ hvt, const __half* __restrict__ hxs,
    const __half* __restrict__ hxst,
    float* __restrict__ t1, float* __restrict__ t2, int stage) {
    extern __shared__ float smf[];
    uint32_t* Ps2 = (uint32_t*)smf;            // 128 x ST2 (Q staging, then P)
    uint32_t* Ks2 = Ps2 + 128 * ST2;           // 64 x ST2
    uint32_t* Vs2 = Ks2 + 64 * ST2;            // 64 x ST2

    // ---- per-z operand selection ----
    const __half *Q, *K, *V;
    float* O;
    int useInvTemp;
    int z = blockIdx.z;
    if (stage == 0) {
        if (z == 0) { Q = hq; K = hk; V = hvt; O = t1; useInvTemp = 0; }
        else {
            const __half* p = hxs + (size_t)(z - 1) * BHND;
            Q = p; K = p;
            V = hxst + (size_t)(z - 1) * VTSZ;
            O = t2 + (size_t)(z - 1) * BHND;
            useInvTemp = 1;
        }
    } else {
        const __half* p = hxs + (size_t)z * BHND;
        Q = p; K = p; V = hvt;
        O = t2 + (size_t)z * BHND;
        useInvTemp = 1;
    }

    int tid = threadIdx.x;
    int warp = tid >> 5, lane = tid & 31;
    int g = lane >> 2, t = lane & 3;
    int bh = blockIdx.y;
    int m0 = blockIdx.x * 128;
    float scale = useInvTemp ? g_invtemp[bh / NHEAD] : 0.125f;
    const float qscale = scale * 1.4426950408889634f;
    const size_t baseQ = (size_t)bh * NTOK * HDIM;
    const size_t baseV = (size_t)bh * HDIM * NTOKP;
    const int rA = warp * 32 + g;
    const int rB = warp * 32 + 16 + g;

    // ---- stage Q (scaled, half) into Ps2 ----
#pragma unroll
    for (int e = 0; e < 8; e++) {
        int idx = tid + e * 128;
        int row = idx >> 3, c8 = idx & 7;
        uint4 v = make_uint4(0, 0, 0, 0);
        if (m0 + row < NTOK)
            v = *(const uint4*)(Q + baseQ + (size_t)(m0 + row) * HDIM + c8 * 8);
        uint32_t* pr = (uint32_t*)&v;
        uint32_t o[4];
#pragma unroll
        for (int i = 0; i < 4; i++) {
            __half2 h; memcpy(&h, &pr[i], 4);
            float2 f = __half22float2(h);
            o[i] = h2u(__floats2half2_rn(f.x * qscale, f.y * qscale));
        }
        Ps2[row * ST2 + c8 * 4 + 0] = o[0];
        Ps2[row * ST2 + c8 * 4 + 1] = o[1];
        Ps2[row * ST2 + c8 * 4 + 2] = o[2];
        Ps2[row * ST2 + c8 * 4 + 3] = o[3];
    }
    __syncthreads();

    // ---- hoist Q fragments (4 k16-chunks) ----
    uint32_t qA[4][4], qB[4][4];
#pragma unroll
    for (int kt = 0; kt < 4; kt++) {
        qA[kt][0] = Ps2[rA * ST2 + kt * 8 + t];
        qA[kt][1] = Ps2[(rA + 8) * ST2 + kt * 8 + t];
        qA[kt][2] = Ps2[rA * ST2 + kt * 8 + t + 4];
        qA[kt][3] = Ps2[(rA + 8) * ST2 + kt * 8 + t + 4];
        qB[kt][0] = Ps2[rB * ST2 + kt * 8 + t];
        qB[kt][1] = Ps2[(rB + 8) * ST2 + kt * 8 + t];
        qB[kt][2] = Ps2[rB * ST2 + kt * 8 + t + 4];
        qB[kt][3] = Ps2[(rB + 8) * ST2 + kt * 8 + t + 4];
    }

    float lA0 = 0.f, lA1 = 0.f, lB0 = 0.f, lB1 = 0.f;
    float oA[8][4], oB[8][4];
#pragma unroll
    for (int nt = 0; nt < 8; nt++)
#pragma unroll
        for (int j = 0; j < 4; j++) { oA[nt][j] = 0.f; oB[nt][j] = 0.f; }

    for (int kt0 = 0; kt0 < NTOK; kt0 += 64) {
        __syncthreads();
        // ---- stage K (key-major) + V (d-major) tiles ----
#pragma unroll
        for (int e = 0; e < 4; e++) {
            int idx = tid + e * 128;
            int row = idx >> 3, c8 = idx & 7;
            uint4 kv = make_uint4(0, 0, 0, 0);
            if (kt0 + row < NTOK)
                kv = *(const uint4*)(K + baseQ + (size_t)(kt0 + row) * HDIM + c8 * 8);
            Ks2[row * ST2 + c8 * 4 + 0] = kv.x;
            Ks2[row * ST2 + c8 * 4 + 1] = kv.y;
            Ks2[row * ST2 + c8 * 4 + 2] = kv.z;
            Ks2[row * ST2 + c8 * 4 + 3] = kv.w;
            // V: row -> d, c8 -> keypair group (always in-bounds, pad is zero)
            uint4 vv = *(const uint4*)(V + baseV + (size_t)row * NTOKP + kt0 + c8 * 8);
            Vs2[row * ST2 + c8 * 4 + 0] = vv.x;
            Vs2[row * ST2 + c8 * 4 + 1] = vv.y;
            Vs2[row * ST2 + c8 * 4 + 2] = vv.z;
            Vs2[row * ST2 + c8 * 4 + 3] = vv.w;
        }
        __syncthreads();

        // ---- S = (Q*qscale) K^T ----
        float sA[8][4], sB[8][4];
#pragma unroll
        for (int nt = 0; nt < 8; nt++)
#pragma unroll
            for (int j = 0; j < 4; j++) { sA[nt][j] = 0.f; sB[nt][j] = 0.f; }

#pragma unroll
        for (int kt = 0; kt < 4; kt++) {
#pragma unroll
            for (int nt = 0; nt < 8; nt++) {
                uint32_t b0 = Ks2[(nt * 8 + g) * ST2 + kt * 8 + t];
                uint32_t b1 = Ks2[(nt * 8 + g) * ST2 + kt * 8 + t + 4];
                mma16(sA[nt], qA[kt][0], qA[kt][1], qA[kt][2], qA[kt][3], b0, b1);
                mma16(sB[nt], qB[kt][0], qB[kt][1], qB[kt][2], qB[kt][3], b0, b1);
            }
        }

        // ---- no-max softmax: p = 2^s ----
        bool tail = (kt0 + 64 > NTOK);
#pragma unroll
        for (int nt = 0; nt < 8; nt++) {
            if (tail) {
                int cg = kt0 + nt * 8 + 2 * t;
                if (cg >= NTOK) {
                    sA[nt][0] = -1e30f; sA[nt][2] = -1e30f;
                    sB[nt][0] = -1e30f; sB[nt][2] = -1e30f;
                }
                if (cg + 1 >= NTOK) {
                    sA[nt][1] = -1e30f; sA[nt][3] = -1e30f;
                    sB[nt][1] = -1e30f; sB[nt][3] = -1e30f;
                }
            }
            float pA0 = ex2(sA[nt][0]);
            float pA1 = ex2(sA[nt][1]);
            float pA2 = ex2(sA[nt][2]);
            float pA3 = ex2(sA[nt][3]);
            float pB0 = ex2(sB[nt][0]);
            float pB1 = ex2(sB[nt][1]);
            float pB2 = ex2(sB[nt][2]);
            float pB3 = ex2(sB[nt][3]);
            lA0 += pA0 + pA1; lA1 += pA2 + pA3;
            lB0 += pB0 + pB1; lB1 += pB2 + pB3;
            int kp = nt * 4 + t;   // keypair column
            Ps2[rA * ST2 + kp]       = h2u(__floats2half2_rn(pA0, pA1));
            Ps2[(rA + 8) * ST2 + kp] = h2u(__floats2half2_rn(pA2, pA3));
            Ps2[rB * ST2 + kp]       = h2u(__floats2half2_rn(pB0, pB1));
            Ps2[(rB + 8) * ST2 + kp] = h2u(__floats2half2_rn(pB2, pB3));
        }
        __syncwarp();

        // ---- O += P V ----
#pragma unroll
        for (int kt = 0; kt < 4; kt++) {
            uint32_t aA0 = Ps2[rA * ST2 + kt * 8 + t];
            uint32_t aA1 = Ps2[(rA + 8) * ST2 + kt * 8 + t];
            uint32_t aA2 = Ps2[rA * ST2 + kt * 8 + t + 4];
            uint32_t aA3 = Ps2[(rA + 8) * ST2 + kt * 8 + t + 4];
            uint32_t aB0 = Ps2[rB * ST2 + kt * 8 + t];
            uint32_t aB1 = Ps2[(rB + 8) * ST2 + kt * 8 + t];
            uint32_t aB2 = Ps2[rB * ST2 + kt * 8 + t + 4];
            uint32_t aB3 = Ps2[(rB + 8) * ST2 + kt * 8 + t + 4];
#pragma unroll
            for (int nt = 0; nt < 8; nt++) {
                uint32_t b0 = Vs2[(nt * 8 + g) * ST2 + kt * 8 + t];
                uint32_t b1 = Vs2[(nt * 8 + g) * ST2 + kt * 8 + t + 4];
                mma16(oA[nt], aA0, aA1, aA2, aA3, b0, b1);
                mma16(oB[nt], aB0, aB1, aB2, aB3, b0, b1);
            }
        }
    }

    // deferred l reduction over the 4 t-lanes of each row group
    lA0 += __shfl_xor_sync(0xffffffffu, lA0, 1);
    lA0 += __shfl_xor_sync(0xffffffffu, lA0, 2);
    lA1 += __shfl_xor_sync(0xffffffffu, lA1, 1);
    lA1 += __shfl_xor_sync(0xffffffffu, lA1, 2);
    lB0 += __shfl_xor_sync(0xffffffffu, lB0, 1);
    lB0 += __shfl_xor_sync(0xffffffffu, lB0, 2);
    lB1 += __shfl_xor_sync(0xffffffffu, lB1, 1);
    lB1 += __shfl_xor_sync(0xffffffffu, lB1, 2);
    float iA0 = 1.f / lA0, iA1 = 1.f / lA1, iB0 = 1.f / lB0, iB1 = 1.f / lB1;
    const size_t baseO = (size_t)bh * NTOK * HDIM;
#pragma unroll
    for (int nt = 0; nt < 8; nt++) {
        int col = nt * 8 + 2 * t;
        int r;
        r = m0 + rA;
        if (r < NTOK)
            *(float2*)(O + baseO + (size_t)r * HDIM + col) =
                make_float2(oA[nt][0] * iA0, oA[nt][1] * iA0);
        r = m0 + rA + 8;
        if (r < NTOK)
            *(float2*)(O + baseO + (size_t)r * HDIM + col) =
                make_float2(oA[nt][2] * iA1, oA[nt][3] * iA1);
        r = m0 + rB;
        if (r < NTOK)
            *(float2*)(O + baseO + (size_t)r * HDIM + col) =
                make_float2(oB[nt][0] * iB0, oB[nt][1] * iB0);
        r = m0 + rB + 8;
        if (r < NTOK)
            *(float2*)(O + baseO + (size_t)r * HDIM + col) =
                make_float2(oB[nt][2] * iB1, oB[nt][3] * iB1);
    }
}

// ---------------- qkv projection GEMM (fp16 m16n8k16, half outputs) ---------
// K-tile 64 floats -> half2 smem, u32 stride 36 (4g+t bank perm).

__global__ __launch_bounds__(128) void qkv_tc(const float* __restrict__ x,
                                              const float* __restrict__ W) {
    __shared__ uint32_t As2[64 * ST2];
    __shared__ uint32_t Bs2[64 * ST2];
    int tid = threadIdx.x;
    int warp = tid >> 5, lane = tid & 31;
    int g = lane >> 2, t = lane & 3;
    int m0 = blockIdx.x * 64;
    int o0 = blockIdx.y * 64;
    int b = blockIdx.z;
    const int r0 = warp * 16 + g;

    float c[8][4];
#pragma unroll
    for (int nt = 0; nt < 8; nt++)
#pragma unroll
        for (int j = 0; j < 4; j++) c[nt][j] = 0.f;

    for (int c0 = 0; c0 < CDIM; c0 += 64) {
        __syncthreads();
#pragma unroll
        for (int e = 0; e < 8; e++) {
            int idx = tid + e * 128;
            int row = idx >> 4;
            int c4 = idx & 15;          // float4 index within 64-col tile
            float4 a4 = make_float4(0.f, 0.f, 0.f, 0.f);
            if (m0 + row < NTOK)
                a4 = *(const float4*)(x + (size_t)(m0 + row) * (BATCH * CDIM) + b * CDIM + c0 + c4 * 4);
            As2[row * ST2 + c4 * 2 + 0] = h2u(__floats2half2_rn(a4.x, a4.y));
            As2[row * ST2 + c4 * 2 + 1] = h2u(__floats2half2_rn(a4.z, a4.w));
            float4 b4 = *(const float4*)(W + (size_t)(o0 + row) * CDIM + c0 + c4 * 4);
            Bs2[row * ST2 + c4 * 2 + 0] = h2u(__floats2half2_rn(b4.x, b4.y));
            Bs2[row * ST2 + c4 * 2 + 1] = h2u(__floats2half2_rn(b4.z, b4.w));
        }
        __syncthreads();

#pragma unroll
        for (int kt = 0; kt < 4; kt++) {
            uint32_t a0 = As2[r0 * ST2 + kt * 8 + t];
            uint32_t a1 = As2[(r0 + 8) * ST2 + kt * 8 + t];
            uint32_t a2 = As2[r0 * ST2 + kt * 8 + t + 4];
            uint32_t a3 = As2[(r0 + 8) * ST2 + kt * 8 + t + 4];
#pragma unroll
            for (int nt = 0; nt < 8; nt++) {
                uint32_t b0 = Bs2[(nt * 8 + g) * ST2 + kt * 8 + t];
                uint32_t b1 = Bs2[(nt * 8 + g) * ST2 + kt * 8 + t + 4];
                mma16(c[nt], a0, a1, a2, a3, b0, b1);
            }
        }
    }

    int tsel = o0 / CDIM;
    int h = (o0 % CDIM) >> 6;
    __half* dst = (tsel == 0) ? g_hq : ((tsel == 1) ? g_hk : g_hv);
    dst += (size_t)((b * NHEAD + h) * NTOK) * HDIM;
    int gr0 = m0 + r0, gr1 = m0 + r0 + 8;
#pragma unroll
    for (int nt = 0; nt < 8; nt++) {
        int col = nt * 8 + 2 * t;
        if (gr0 < NTOK)
            *(__half2*)&dst[(size_t)gr0 * HDIM + col] =
                __floats2half2_rn(c[nt][0], c[nt][1]);
        if (gr1 < NTOK)
            *(__half2*)&dst[(size_t)gr1 * HDIM + col] =
                __floats2half2_rn(c[nt][2], c[nt][3]);
    }
}

// ---------------- output projection GEMM (fp16 TC; z-batched both outputs) --
__global__ __launch_bounds__(128) void proj_tc(const float* __restrict__ t1,
                                               const float* __restrict__ t2,
                                               const float* __restrict__ W,
                                               const float* __restrict__ bias,
                                               float* __restrict__ outbase) {
    __shared__ uint32_t As2[64 * ST2];
    __shared__ uint32_t Bs2[64 * ST2];
    int tid = threadIdx.x;
    int warp = tid >> 5, lane = tid & 31;
    int g = lane >> 2, t = lane & 3;
    int m0 = blockIdx.x * 64;
    int o0 = blockIdx.y * 64;
    int zb = blockIdx.z;
    int b = zb & 7;
    int which = zb >> 3;
    const float* s0 = which ? t2 : t1;
    const float* s1 = which ? (t2 + BHND) : nullptr;
    const float* s2 = which ? (t2 + 2 * BHND) : nullptr;
    float* out = which ? outbase : (outbase + NBC);
    float prescale = which ? (1.0f / 3.0f) : 1.0f;
    const int r0 = warp * 16 + g;

    float c[8][4];
#pragma unroll
    for (int nt = 0; nt < 8; nt++)
#pragma unroll
        for (int j = 0; j < 4; j++) c[nt][j] = 0.f;

    for (int c0 = 0; c0 < CDIM; c0 += 64) {
        int h = c0 >> 6;   // c0 is a multiple of 64 -> exactly one head per tile
        __syncthreads();
#pragma unroll
        for (int e = 0; e < 8; e++) {
            int idx = tid + e * 128;
            int row = idx >> 4;
            int c4 = idx & 15;
            float4 a4 = make_float4(0.f, 0.f, 0.f, 0.f);
            if (m0 + row < NTOK) {
                size_t off = (size_t)((b * NHEAD + h) * NTOK + m0 + row) * HDIM + c4 * 4;
                a4 = *(const float4*)(s0 + off);
                if (s1) {
                    float4 a1 = *(const float4*)(s1 + off);
                    float4 a2 = *(const float4*)(s2 + off);
                    a4.x += a1.x + a2.x; a4.y += a1.y + a2.y;
                    a4.z += a1.z + a2.z; a4.w += a1.w + a2.w;
                }
            }
            As2[row * ST2 + c4 * 2 + 0] = h2u(__floats2half2_rn(a4.x, a4.y));
            As2[row * ST2 + c4 * 2 + 1] = h2u(__floats2half2_rn(a4.z, a4.w));
            float4 b4 = *(const float4*)(W + (size_t)(o0 + row) * CDIM + c0 + c4 * 4);
            Bs2[row * ST2 + c4 * 2 + 0] = h2u(__floats2half2_rn(b4.x, b4.y));
            Bs2[row * ST2 + c4 * 2 + 1] = h2u(__floats2half2_rn(b4.z, b4.w));
        }
        __syncthreads();

#pragma unroll
        for (int kt = 0; kt < 4; kt++) {
            uint32_t a0 = As2[r0 * ST2 + kt * 8 + t];
            uint32_t a1 = As2[(r0 + 8) * ST2 + kt * 8 + t];
            uint32_t a2 = As2[r0 * ST2 + kt * 8 + t + 4];
            uint32_t a3 = As2[(r0 + 8) * ST2 + kt * 8 + t + 4];
#pragma unroll
            for (int nt = 0; nt < 8; nt++) {
                uint32_t b0 = Bs2[(nt * 8 + g) * ST2 + kt * 8 + t];
                uint32_t b1 = Bs2[(nt * 8 + g) * ST2 + kt * 8 + t + 4];
                mma16(c[nt], a0, a1, a2, a3, b0, b1);
            }
        }
    }

    int gr0 = m0 + r0, gr1 = m0 + r0 + 8;
#pragma unroll
    for (int nt = 0; nt < 8; nt++) {
        int col = nt * 8 + 2 * t;
        float b0 = bias[o0 + col], b1 = bias[o0 + col + 1];
        if (gr0 < NTOK)
            *(float2*)(out + (size_t)gr0 * (BATCH * CDIM) + b * CDIM + o0 + col) =
                make_float2(c[nt][0] * prescale + b0, c[nt][1] * prescale + b1);
        if (gr1 < NTOK)
            *(float2*)(out + (size_t)gr1 * (BATCH * CDIM) + b * CDIM + o0 + col) =
                make_float2(c[nt][2] * prescale + b0, c[nt][3] * prescale + b1);
    }
}

// ---------------- host orchestration ---------------------------------------
extern "C" void kernel_launch(void* const* d_in, const int* in_sizes, int n_in,
                              void* d_out, int out_size) {
    const float* x = (const float*)d_in[0];
    const float* Wqkv = (const float*)d_in[1];
    const float* Wproj = (const float*)d_in[2];
    const float* bproj = (const float*)d_in[3];
    float* out = (float*)d_out;

    cudaFuncSetAttribute(attn_tc, cudaFuncAttributeMaxDynamicSharedMemorySize,
                         ATT_SMEM);

    __half *hq, *hk, *hv, *hvt, *hxs, *hxst;
    float *t1, *t2;
    cudaGetSymbolAddress((void**)&hq, g_hq);
    cudaGetSymbolAddress((void**)&hk, g_hk);
    cudaGetSymbolAddress((void**)&hv, g_hv);
    cudaGetSymbolAddress((void**)&hvt, g_hvt);
    cudaGetSymbolAddress((void**)&hxs, g_hxs);
    cudaGetSymbolAddress((void**)&hxst, g_hxst);
    cudaGetSymbolAddress((void**)&t1, g_t1);
    cudaGetSymbolAddress((void**)&t2, g_t2);

    const int LN3_GRID = (3 * BH * NTOK * 32 + 255) / 256;
    dim3 ga1((NTOK + 127) / 128, BH, 4);   // stage 0: ori + 3 branches
    dim3 ga2((NTOK + 127) / 128, BH, 3);   // stage 1: 3 branches
    dim3 gq((NTOK + 63) / 64, 36, BATCH);
    dim3 gp((NTOK + 63) / 64, 12, 2 * BATCH);
    dim3 gtv(NTOKP / 64, BH);              // transpose v
    dim3 gtx(NTOKP / 64, 3 * BH);          // transpose xs

    rownorm_kernel<<<(BATCH * NTOK * 32 + 255) / 256, 256>>>(x);
    invtemp_kernel<<<BATCH, 256>>>();

    qkv_tc<<<gq, 128>>>(x, Wqkv);

    // v -> vt; l2norm(v,k,q) -> xs; xs -> xst
    transpose_kernel<<<gtv, 128>>>(hv, hvt);
    l2norm3_h<<<LN3_GRID, 256>>>(hv, hk, hq, hxs);
    transpose_kernel<<<gtx, 128>>>(hxs, hxst);

    // stage 0: ori-attn (z=0) + 3 branch stage-1 attns (z=1..3)
    attn_tc<<<ga1, 128, ATT_SMEM>>>(hq, hk, hvt, hxs, hxst, t1, t2, 0);

    // re-normalize branch outputs, stage 1 (z=0..2), V = vt
    l2norm3_f<<<LN3_GRID, 256>>>(t2, hxs);
    attn_tc<<<ga2, 128, ATT_SMEM>>>(hq, hk, hvt, hxs, hxst, t1, t2, 1);

    // both projections in one launch: x_ori from t1, x_out from summed t2
    proj_tc<<<gp, 128>>>(t1, t2, Wproj, bproj, out);
}